// round 6
// baseline (speedup 1.0000x reference)
#include <cuda_runtime.h>
#include <cuda_fp16.h>
#include <cstdint>

// Problem constants
#define B_   8
#define H_   8
#define S_   4096
#define D_   64
#define DM_  768
#define SM2  (S_ - 2)            // 4094
#define ROWS_TOTAL (B_ * SM2)    // 32752
#define CHUNKS 64
#define ROWS_PER_CHUNK 512
#define DENOM ((float)(B_ * SM2))

#define MROWS (B_ * S_)          // 32768
#define KDIM  (H_ * D_)          // 512

// ---------------------------------------------------------------------------
// Static device scratch (allocation-free per harness rules)
// ---------------------------------------------------------------------------
__device__ float g_scratch[H_][CHUNKS][2][D_ * D_];
__device__ float g_G[H_][D_ * D_];
__device__ float g_U[H_][D_ * D_];
__device__ float g_NT[H_][D_ * D_];
__device__ __align__(16) __half g_Ahi[(size_t)MROWS * KDIM];
__device__ __align__(16) __half g_Alo[(size_t)MROWS * KDIM];
__device__ __align__(16) __half g_Bhi[(size_t)DM_ * KDIM];

// ---------------------------------------------------------------------------
// Helpers
// ---------------------------------------------------------------------------
__device__ __forceinline__ uint32_t smem_to_u32(const void* p) {
    uint32_t a;
    asm("{ .reg .u64 t; cvta.to.shared.u64 t, %1; cvt.u32.u64 %0, t; }" : "=r"(a) : "l"(p));
    return a;
}
__device__ __forceinline__ unsigned long long dup_f32x2(float x) {
    unsigned long long r;
    asm("mov.b64 %0, {%1, %1};" : "=l"(r) : "r"(__float_as_uint(x)));
    return r;
}
__device__ __forceinline__ unsigned long long pack_f32x2(float lo, float hi) {
    unsigned long long r;
    asm("mov.b64 %0, {%1, %2};" : "=l"(r) : "r"(__float_as_uint(lo)), "r"(__float_as_uint(hi)));
    return r;
}
__device__ __forceinline__ void fma_f32x2(unsigned long long& d, unsigned long long a, unsigned long long b) {
    asm("fma.rn.f32x2 %0, %1, %2, %0;" : "+l"(d) : "l"(a), "l"(b));
}
__device__ __forceinline__ unsigned long long mul_f32x2(unsigned long long a, unsigned long long b) {
    unsigned long long r;
    asm("mul.rn.f32x2 %0, %1, %2;" : "=l"(r) : "l"(a), "l"(b));
    return r;
}
__device__ __forceinline__ void unpack_f32x2(float& lo, float& hi, unsigned long long v) {
    uint32_t l, h;
    asm("mov.b64 {%0, %1}, %2;" : "=r"(l), "=r"(h) : "l"(v));
    lo = __uint_as_float(l); hi = __uint_as_float(h);
}
__device__ __forceinline__ void mma_16816_f16(float* c, const uint32_t* a, const uint32_t* b) {
    asm volatile(
        "mma.sync.aligned.m16n8k16.row.col.f32.f16.f16.f32 "
        "{%0,%1,%2,%3}, {%4,%5,%6,%7}, {%8,%9}, {%0,%1,%2,%3};"
        : "+f"(c[0]), "+f"(c[1]), "+f"(c[2]), "+f"(c[3])
        : "r"(a[0]), "r"(a[1]), "r"(a[2]), "r"(a[3]), "r"(b[0]), "r"(b[1]));
}
#define CP_ASYNC_16(smem_u32, gptr) \
    asm volatile("cp.async.cg.shared.global [%0], [%1], 16;" :: "r"(smem_u32), "l"(gptr))
#define CP_ASYNC_COMMIT() asm volatile("cp.async.commit_group;")
#define CP_ASYNC_WAIT(n)  asm volatile("cp.async.wait_group %0;" :: "n"(n))

// ---------------------------------------------------------------------------
// Kernel A1: Qaddr (shift-by-1) -> fp16 hi/lo split A matrix [m][k]
// ---------------------------------------------------------------------------
__global__ __launch_bounds__(256) void prepA(const float* __restrict__ Q) {
    const int idx = blockIdx.x * 256 + threadIdx.x;     // < 8*8*4095*16
    const int c4  = idx & 15;
    const int rst = idx >> 4;
    const int s   = rst % (S_ - 1);                     // 0..4094
    const int bh  = rst / (S_ - 1);
    const int h   = bh & 7;
    const int b   = bh >> 3;
    const float4 v = *(const float4*)(Q + (((size_t)(b * H_ + h)) * S_ + s) * D_ + c4 * 4);
    const size_t m = (size_t)b * S_ + s + 1;
    const size_t o = m * KDIM + h * 64 + c4 * 4;
    float x[4] = {v.x, v.y, v.z, v.w};
    __half hi[4], lo[4];
#pragma unroll
    for (int i = 0; i < 4; ++i) {
        hi[i] = __float2half_rn(x[i]);
        lo[i] = __float2half_rn(x[i] - __half2float(hi[i]));
    }
    *(__half2*)(g_Ahi + o)     = __halves2half2(hi[0], hi[1]);
    *(__half2*)(g_Ahi + o + 2) = __halves2half2(hi[2], hi[3]);
    *(__half2*)(g_Alo + o)     = __halves2half2(lo[0], lo[1]);
    *(__half2*)(g_Alo + o + 2) = __halves2half2(lo[2], lo[3]);
}

__global__ __launch_bounds__(256) void zeroA() {
    const int idx = blockIdx.x * 256 + threadIdx.x;     // < 8*512
    const int b = idx >> 9, col = idx & 511;
    const size_t o = (size_t)b * S_ * KDIM + col;
    g_Ahi[o] = __float2half(0.f);
    g_Alo[o] = __float2half(0.f);
}

// ---------------------------------------------------------------------------
// Kernel 1: per-(head, chunk) partial Gram sums (f32x2 packed accumulation).
// ---------------------------------------------------------------------------
__global__ __launch_bounds__(256) void gram_partial(const float* __restrict__ Q,
                                                    const float* __restrict__ V) {
    const int c = blockIdx.x;
    const int h = blockIdx.y;
    const int t = threadIdx.x;

    __shared__ float sq[8][64];
    __shared__ float sv[8][64];
    __shared__ float sinv[8];

    const int p0 = (t >> 4) * 4;
    const int q0 = (t & 15) * 4;

    unsigned long long aG[4][2], aU[4][2];
#pragma unroll
    for (int i = 0; i < 4; ++i) { aG[i][0] = aG[i][1] = 0ull; aU[i][0] = aU[i][1] = 0ull; }

    const int rbase = c * ROWS_PER_CHUNK;
    const int which = t >> 7;
    const int li    = t & 127;
    const int lrow  = li >> 4;
    const int lf4   = li & 15;

    for (int it = 0; it < ROWS_PER_CHUNK / 8; ++it) {
        const int r8 = rbase + it * 8;
        {
            const int r = r8 + lrow;
            float4 val = make_float4(0.f, 0.f, 0.f, 0.f);
            if (r < ROWS_TOTAL) {
                const int b = r / SM2;
                const int i = r - b * SM2;
                if (which == 0)
                    val = *(const float4*)(Q + (((size_t)(b * H_ + h)) * S_ + i) * D_ + lf4 * 4);
                else
                    val = *(const float4*)(V + (((size_t)(b * H_ + h)) * S_ + (i + 2)) * D_ + lf4 * 4);
            }
            float* dst = (which == 0) ? &sq[lrow][lf4 * 4] : &sv[lrow][lf4 * 4];
            *(float4*)dst = val;
        }
        __syncthreads();
        {
            const int w = t >> 5, lane = t & 31;
            float e0 = sq[w][lane], e1 = sq[w][lane + 32];
            float ss = e0 * e0 + e1 * e1;
#pragma unroll
            for (int off = 16; off > 0; off >>= 1)
                ss += __shfl_xor_sync(0xffffffffu, ss, off);
            if (lane == 0) sinv[w] = 1.0f / fmaxf(sqrtf(ss), 1e-8f);
        }
        __syncthreads();
#pragma unroll 4
        for (int r = 0; r < 8; ++r) {
            const float inv2 = sinv[r] * sinv[r];
            // vectorized fragment loads (LDS.128 x3)
            const float4 qp4 = *(const float4*)&sq[r][p0];
            const float4 qq4 = *(const float4*)&sq[r][q0];
            const float4 vv4 = *(const float4*)&sv[r][q0];
            unsigned long long qqp[2], vvp[2];
            qqp[0] = pack_f32x2(qq4.x, qq4.y);
            qqp[1] = pack_f32x2(qq4.z, qq4.w);
            vvp[0] = pack_f32x2(vv4.x, vv4.y);
            vvp[1] = pack_f32x2(vv4.z, vv4.w);
            const unsigned long long d2 = dup_f32x2(inv2);
            unsigned long long gb[2];
            gb[0] = mul_f32x2(qqp[0], d2);
            gb[1] = mul_f32x2(qqp[1], d2);
            unsigned long long da[4];
            da[0] = dup_f32x2(qp4.x);
            da[1] = dup_f32x2(qp4.y);
            da[2] = dup_f32x2(qp4.z);
            da[3] = dup_f32x2(qp4.w);
#pragma unroll
            for (int i = 0; i < 4; ++i) {
                fma_f32x2(aG[i][0], da[i], gb[0]);
                fma_f32x2(aG[i][1], da[i], gb[1]);
                fma_f32x2(aU[i][0], da[i], vvp[0]);
                fma_f32x2(aU[i][1], da[i], vvp[1]);
            }
        }
        __syncthreads();
    }

    float* oG = g_scratch[h][c][0];
    float* oU = g_scratch[h][c][1];
#pragma unroll
    for (int i = 0; i < 4; ++i) {
        float4 vg, vu;
        unpack_f32x2(vg.x, vg.y, aG[i][0]);
        unpack_f32x2(vg.z, vg.w, aG[i][1]);
        unpack_f32x2(vu.x, vu.y, aU[i][0]);
        unpack_f32x2(vu.z, vu.w, aU[i][1]);
        *(float4*)&oG[(p0 + i) * 64 + q0] = vg;
        *(float4*)&oU[(p0 + i) * 64 + q0] = vu;
    }
}

// ---------------------------------------------------------------------------
// Kernel 2: reduce chunk partials (4-way MLP accumulators).
// ---------------------------------------------------------------------------
__global__ __launch_bounds__(256) void reduce_gram() {
    const int h = blockIdx.y;
    const int e = blockIdx.x * 256 + threadIdx.x;
    float sg0 = 0.f, sg1 = 0.f, sg2 = 0.f, sg3 = 0.f;
    float su0 = 0.f, su1 = 0.f, su2 = 0.f, su3 = 0.f;
#pragma unroll 4
    for (int c = 0; c < CHUNKS; c += 4) {
        sg0 += g_scratch[h][c + 0][0][e];
        sg1 += g_scratch[h][c + 1][0][e];
        sg2 += g_scratch[h][c + 2][0][e];
        sg3 += g_scratch[h][c + 3][0][e];
        su0 += g_scratch[h][c + 0][1][e];
        su1 += g_scratch[h][c + 1][1][e];
        su2 += g_scratch[h][c + 2][1][e];
        su3 += g_scratch[h][c + 3][1][e];
    }
    g_G[h][e] = (sg0 + sg1) + (sg2 + sg3);
    g_U[h][e] = (su0 + su1) + (su2 + su3);
}

// ---------------------------------------------------------------------------
// Kernel 3: new_trace = 0.99*(trace - (G/denom)@trace) + 0.1*U/denom
// ---------------------------------------------------------------------------
__global__ __launch_bounds__(256) void combine_trace(const float* __restrict__ trace) {
    const int h = blockIdx.x;
    const int t = threadIdx.x;
    __shared__ float Gs[4096];
    __shared__ float Ts[4096];
#pragma unroll
    for (int j = 0; j < 16; ++j) {
        Gs[t + 256 * j] = g_G[h][t + 256 * j];
        Ts[t + 256 * j] = trace[h * 4096 + t + 256 * j];
    }
    __syncthreads();
    const float invd = 1.0f / DENOM;
#pragma unroll
    for (int j = 0; j < 16; ++j) {
        const int e = t + 256 * j;
        const int p = e >> 6, q = e & 63;
        float acc = 0.f;
#pragma unroll 8
        for (int k = 0; k < 64; ++k)
            acc += Gs[p * 64 + k] * Ts[k * 64 + q];
        g_NT[h][e] = 0.99f * (Ts[e] - acc * invd) + 0.1f * g_U[h][e] * invd;
    }
}

// ---------------------------------------------------------------------------
// Kernel 4: B[n][h*64+p] = sum_q NT[h][p][q] * W[n][h*64+q] -> fp16 (hi only).
// grid (12, 8), register-tiled 4x4.
// ---------------------------------------------------------------------------
__global__ __launch_bounds__(256) void build_M(const float* __restrict__ W) {
    const int h  = blockIdx.y;
    const int n0 = blockIdx.x * 64;
    const int t  = threadIdx.x;
    __shared__ float Wq[64][72];   // [q][n]
    __shared__ float Nq[64][72];   // [q][p]
#pragma unroll
    for (int j = 0; j < 4; ++j) {
        const int idx = t + j * 256;
        const int row = idx >> 4;
        const int q4  = (idx & 15) * 4;
        float4 wv = *(const float4*)(W + (size_t)(n0 + row) * KDIM + h * 64 + q4);
        Wq[q4 + 0][row] = wv.x; Wq[q4 + 1][row] = wv.y;
        Wq[q4 + 2][row] = wv.z; Wq[q4 + 3][row] = wv.w;
        float4 nv = *(const float4*)(&g_NT[h][row * 64 + q4]);
        Nq[q4 + 0][row] = nv.x; Nq[q4 + 1][row] = nv.y;
        Nq[q4 + 2][row] = nv.z; Nq[q4 + 3][row] = nv.w;
    }
    __syncthreads();
    const int tx = t & 15;     // p block
    const int ty = t >> 4;     // n block
    float acc[4][4];
#pragma unroll
    for (int i = 0; i < 4; ++i)
#pragma unroll
        for (int j = 0; j < 4; ++j) acc[i][j] = 0.f;
#pragma unroll 8
    for (int q = 0; q < 64; ++q) {
        const float4 wv = *(const float4*)&Wq[q][ty * 4];
        const float4 nv = *(const float4*)&Nq[q][tx * 4];
        const float w[4] = {wv.x, wv.y, wv.z, wv.w};
        const float nn[4] = {nv.x, nv.y, nv.z, nv.w};
#pragma unroll
        for (int i = 0; i < 4; ++i)
#pragma unroll
            for (int j = 0; j < 4; ++j)
                acc[i][j] += w[i] * nn[j];
    }
#pragma unroll
    for (int i = 0; i < 4; ++i) {
        const int n = n0 + ty * 4 + i;
#pragma unroll
        for (int j = 0; j < 4; ++j) {
            const int k = h * 64 + tx * 4 + j;
            g_Bhi[(size_t)n * KDIM + k] = __float2half_rn(acc[i][j]);
        }
    }
}

// ---------------------------------------------------------------------------
// Kernel 5: out = (Ahi + Alo) @ Bhi^T via mma.sync fp16 (2-term split,
// 16 K-chunks). BM=BN=128, BK=64, 8 warps (2x4), double-buffered cp.async.
// ---------------------------------------------------------------------------
#define STG_BYTES 36864                         // (128*72 + 128*72) * 2B
#define GEMM_SMEM (2 * STG_BYTES)               // 73728

__global__ __launch_bounds__(256, 2) void out_gemm_mma(float* __restrict__ out) {
    extern __shared__ __align__(16) char smem[];
    const int t = threadIdx.x;
    const int n_base = blockIdx.x * 128;
    const int m_base = blockIdx.y * 128;
    const uint32_t sbase = smem_to_u32(smem);

    const int lrow = t >> 3;        // 0..31 base row for loads (x4 iters)
    const int lc8  = t & 7;         // 16B chunk within 64-col row

    // chunk kc in 0..15:  k0 = (kc/2)*64 ; term = kc%2 (0: Ahi, 1: Alo); B = Bhi
    auto load_stage = [&](int kc, int stage) {
        const int k0 = (kc >> 1) * 64;
        const __half* Ag = ((kc & 1) ? g_Alo : g_Ahi);
        const uint32_t sa = sbase + stage * STG_BYTES;
        const uint32_t sb = sa + 128 * 144;
#pragma unroll
        for (int i = 0; i < 4; ++i) {
            const int row = lrow + i * 32;
            const __half* g = Ag + (((size_t)(m_base + row)) << 9) + k0 + lc8 * 8;
            CP_ASYNC_16(sa + row * 144 + lc8 * 16, g);
        }
#pragma unroll
        for (int i = 0; i < 4; ++i) {
            const int row = lrow + i * 32;
            const __half* g = g_Bhi + (((size_t)(n_base + row)) << 9) + k0 + lc8 * 8;
            CP_ASYNC_16(sb + row * 144 + lc8 * 16, g);
        }
        CP_ASYNC_COMMIT();
    };

    const int wid = t >> 5, lane = t & 31;
    const int wm = wid >> 2;        // 0..1  (64 m-rows)
    const int wn = wid & 3;         // 0..3  (32 n-cols)
    const int fr = lane >> 2;       // 0..7
    const int fcb = (lane & 3) * 4; // k byte offset (2 fp16)

    float acc[4][4][4];
#pragma unroll
    for (int mi = 0; mi < 4; ++mi)
#pragma unroll
        for (int ni = 0; ni < 4; ++ni)
#pragma unroll
            for (int j = 0; j < 4; ++j) acc[mi][ni][j] = 0.f;

    load_stage(0, 0);
    for (int kc = 0; kc < 16; ++kc) {
        if (kc + 1 < 16) {
            load_stage(kc + 1, (kc + 1) & 1);
            CP_ASYNC_WAIT(1);
        } else {
            CP_ASYNC_WAIT(0);
        }
        __syncthreads();

        const char* As = smem + (kc & 1) * STG_BYTES;
        const char* Bs = As + 128 * 144;
#pragma unroll
        for (int kk = 0; kk < 4; ++kk) {
            const int cb = kk * 32 + fcb;        // k16-step byte offset
            uint32_t a[4][4];
#pragma unroll
            for (int mi = 0; mi < 4; ++mi) {
                const int r = wm * 64 + mi * 16 + fr;
                a[mi][0] = *(const uint32_t*)(As + r * 144 + cb);
                a[mi][1] = *(const uint32_t*)(As + (r + 8) * 144 + cb);
                a[mi][2] = *(const uint32_t*)(As + r * 144 + cb + 16);
                a[mi][3] = *(const uint32_t*)(As + (r + 8) * 144 + cb + 16);
            }
            uint32_t b[4][2];
#pragma unroll
            for (int ni = 0; ni < 4; ++ni) {
                const int n = wn * 32 + ni * 8 + fr;
                b[ni][0] = *(const uint32_t*)(Bs + n * 144 + cb);
                b[ni][1] = *(const uint32_t*)(Bs + n * 144 + cb + 16);
            }
#pragma unroll
            for (int mi = 0; mi < 4; ++mi)
#pragma unroll
                for (int ni = 0; ni < 4; ++ni)
                    mma_16816_f16(acc[mi][ni], a[mi], b[ni]);
        }
        __syncthreads();
    }

    // Epilogue: c0,c1 -> (r, c..c+1); c2,c3 -> (r+8, c..c+1)
#pragma unroll
    for (int mi = 0; mi < 4; ++mi) {
        const int r = m_base + wm * 64 + mi * 16 + fr;
#pragma unroll
        for (int ni = 0; ni < 4; ++ni) {
            const int cg = n_base + wn * 32 + ni * 8 + (lane & 3) * 2;
            *(float2*)(out + (size_t)r * DM_ + cg) =
                make_float2(acc[mi][ni][0], acc[mi][ni][1]);
            *(float2*)(out + (size_t)(r + 8) * DM_ + cg) =
                make_float2(acc[mi][ni][2], acc[mi][ni][3]);
        }
    }
}

// ---------------------------------------------------------------------------
extern "C" void kernel_launch(void* const* d_in, const int* in_sizes, int n_in,
                              void* d_out, int out_size) {
    const float* Q     = (const float*)d_in[0];
    const float* V     = (const float*)d_in[1];
    const float* trace = (const float*)d_in[2];
    const float* W     = (const float*)d_in[3];
    float* out = (float*)d_out;

    static bool attr_set = false;
    if (!attr_set) {
        cudaFuncSetAttribute(out_gemm_mma, cudaFuncAttributeMaxDynamicSharedMemorySize, GEMM_SMEM);
        attr_set = true;
    }

    prepA<<<(B_ * H_ * (S_ - 1) * 16) / 256, 256>>>(Q);
    zeroA<<<(B_ * KDIM) / 256, 256>>>();
    gram_partial<<<dim3(CHUNKS, H_), 256>>>(Q, V);
    reduce_gram<<<dim3(16, H_), 256>>>();
    combine_trace<<<H_, 256>>>(trace);
    build_M<<<dim3(12, H_), 256>>>(W);
    out_gemm_mma<<<dim3(DM_ / 128, MROWS / 128), 256, GEMM_SMEM>>>(out);
}

// round 7
// speedup vs baseline: 1.3939x; 1.3939x over previous
#include <cuda_runtime.h>
#include <cuda_fp16.h>
#include <cstdint>

// Problem constants
#define B_   8
#define H_   8
#define S_   4096
#define D_   64
#define DM_  768
#define SM2  (S_ - 2)            // 4094
#define ROWS_TOTAL (B_ * SM2)    // 32752
#define CHUNKS 64
#define ROWS_PER_CHUNK 512
#define DENOM ((float)(B_ * SM2))

#define MROWS (B_ * S_)          // 32768
#define KDIM  (H_ * D_)          // 512

// ---------------------------------------------------------------------------
// Static device scratch (allocation-free per harness rules)
// ---------------------------------------------------------------------------
__device__ float g_scratch[H_][CHUNKS][2][D_ * D_];
__device__ float g_G[H_][D_ * D_];
__device__ float g_U[H_][D_ * D_];
__device__ float g_NT[H_][D_ * D_];
__device__ __align__(16) __half g_Ahi[(size_t)MROWS * KDIM];
__device__ __align__(16) __half g_Alo[(size_t)MROWS * KDIM];
__device__ __align__(16) __half g_Bhi[(size_t)DM_ * KDIM];

// ---------------------------------------------------------------------------
// Helpers
// ---------------------------------------------------------------------------
__device__ __forceinline__ uint32_t smem_to_u32(const void* p) {
    uint32_t a;
    asm("{ .reg .u64 t; cvta.to.shared.u64 t, %1; cvt.u32.u64 %0, t; }" : "=r"(a) : "l"(p));
    return a;
}
__device__ __forceinline__ unsigned long long dup_f32x2(float x) {
    unsigned long long r;
    asm("mov.b64 %0, {%1, %1};" : "=l"(r) : "r"(__float_as_uint(x)));
    return r;
}
__device__ __forceinline__ void fma_f32x2(unsigned long long& d, unsigned long long a, unsigned long long b) {
    asm("fma.rn.f32x2 %0, %1, %2, %0;" : "+l"(d) : "l"(a), "l"(b));
}
__device__ __forceinline__ unsigned long long mul_f32x2(unsigned long long a, unsigned long long b) {
    unsigned long long r;
    asm("mul.rn.f32x2 %0, %1, %2;" : "=l"(r) : "l"(a), "l"(b));
    return r;
}
__device__ __forceinline__ void unpack_f32x2(float& lo, float& hi, unsigned long long v) {
    uint32_t l, h;
    asm("mov.b64 {%0, %1}, %2;" : "=r"(l), "=r"(h) : "l"(v));
    lo = __uint_as_float(l); hi = __uint_as_float(h);
}
__device__ __forceinline__ void mma_16816_f16(float* c, const uint32_t* a, const uint32_t* b) {
    asm volatile(
        "mma.sync.aligned.m16n8k16.row.col.f32.f16.f16.f32 "
        "{%0,%1,%2,%3}, {%4,%5,%6,%7}, {%8,%9}, {%0,%1,%2,%3};"
        : "+f"(c[0]), "+f"(c[1]), "+f"(c[2]), "+f"(c[3])
        : "r"(a[0]), "r"(a[1]), "r"(a[2]), "r"(a[3]), "r"(b[0]), "r"(b[1]));
}
#define CP_ASYNC_16(smem_u32, gptr) \
    asm volatile("cp.async.cg.shared.global [%0], [%1], 16;" :: "r"(smem_u32), "l"(gptr))
#define CP_ASYNC_COMMIT() asm volatile("cp.async.commit_group;")
#define CP_ASYNC_WAIT(n)  asm volatile("cp.async.wait_group %0;" :: "n"(n))

// ---------------------------------------------------------------------------
// Kernel A1: Qaddr (shift-by-1) -> fp16 hi/lo split A matrix [m][k]
// ---------------------------------------------------------------------------
__global__ __launch_bounds__(256) void prepA(const float* __restrict__ Q) {
    const int idx = blockIdx.x * 256 + threadIdx.x;     // < 8*8*4095*16
    const int c4  = idx & 15;
    const int rst = idx >> 4;
    const int s   = rst % (S_ - 1);                     // 0..4094
    const int bh  = rst / (S_ - 1);
    const int h   = bh & 7;
    const int b   = bh >> 3;
    const float4 v = *(const float4*)(Q + (((size_t)(b * H_ + h)) * S_ + s) * D_ + c4 * 4);
    const size_t m = (size_t)b * S_ + s + 1;
    const size_t o = m * KDIM + h * 64 + c4 * 4;
    float x[4] = {v.x, v.y, v.z, v.w};
    __half hi[4], lo[4];
#pragma unroll
    for (int i = 0; i < 4; ++i) {
        hi[i] = __float2half_rn(x[i]);
        lo[i] = __float2half_rn(x[i] - __half2float(hi[i]));
    }
    *(__half2*)(g_Ahi + o)     = __halves2half2(hi[0], hi[1]);
    *(__half2*)(g_Ahi + o + 2) = __halves2half2(hi[2], hi[3]);
    *(__half2*)(g_Alo + o)     = __halves2half2(lo[0], lo[1]);
    *(__half2*)(g_Alo + o + 2) = __halves2half2(lo[2], lo[3]);
}

__global__ __launch_bounds__(256) void zeroA() {
    const int idx = blockIdx.x * 256 + threadIdx.x;     // < 8*512
    const int b = idx >> 9, col = idx & 511;
    const size_t o = (size_t)b * S_ * KDIM + col;
    g_Ahi[o] = __float2half(0.f);
    g_Alo[o] = __float2half(0.f);
}

// ---------------------------------------------------------------------------
// Kernel 1: per-(head, chunk) partial Gram sums — EXACT R5 version (493 µs run)
// ---------------------------------------------------------------------------
__global__ __launch_bounds__(256) void gram_partial(const float* __restrict__ Q,
                                                    const float* __restrict__ V) {
    const int c = blockIdx.x;
    const int h = blockIdx.y;
    const int t = threadIdx.x;

    __shared__ float sq[8][64];
    __shared__ float sv[8][64];
    __shared__ float sinv[8];

    const int p0 = (t >> 4) * 4;
    const int q0 = (t & 15) * 4;

    unsigned long long aG[4][2], aU[4][2];
#pragma unroll
    for (int i = 0; i < 4; ++i) { aG[i][0] = aG[i][1] = 0ull; aU[i][0] = aU[i][1] = 0ull; }

    const int rbase = c * ROWS_PER_CHUNK;
    const int which = t >> 7;
    const int li    = t & 127;
    const int lrow  = li >> 4;
    const int lf4   = li & 15;

    for (int it = 0; it < ROWS_PER_CHUNK / 8; ++it) {
        const int r8 = rbase + it * 8;
        {
            const int r = r8 + lrow;
            float4 val = make_float4(0.f, 0.f, 0.f, 0.f);
            if (r < ROWS_TOTAL) {
                const int b = r / SM2;
                const int i = r - b * SM2;
                if (which == 0)
                    val = *(const float4*)(Q + (((size_t)(b * H_ + h)) * S_ + i) * D_ + lf4 * 4);
                else
                    val = *(const float4*)(V + (((size_t)(b * H_ + h)) * S_ + (i + 2)) * D_ + lf4 * 4);
            }
            float* dst = (which == 0) ? &sq[lrow][lf4 * 4] : &sv[lrow][lf4 * 4];
            *(float4*)dst = val;
        }
        __syncthreads();
        {
            const int w = t >> 5, lane = t & 31;
            float e0 = sq[w][lane], e1 = sq[w][lane + 32];
            float ss = e0 * e0 + e1 * e1;
#pragma unroll
            for (int off = 16; off > 0; off >>= 1)
                ss += __shfl_xor_sync(0xffffffffu, ss, off);
            if (lane == 0) sinv[w] = 1.0f / fmaxf(sqrtf(ss), 1e-8f);
        }
        __syncthreads();
#pragma unroll 4
        for (int r = 0; r < 8; ++r) {
            const float inv  = sinv[r];
            const float inv2 = inv * inv;
            float qp[4];
#pragma unroll
            for (int i = 0; i < 4; ++i) qp[i] = sq[r][p0 + i];
            unsigned long long qqp[2], vvp[2];
            qqp[0] = *(const unsigned long long*)&sq[r][q0];
            qqp[1] = *(const unsigned long long*)&sq[r][q0 + 2];
            vvp[0] = *(const unsigned long long*)&sv[r][q0];
            vvp[1] = *(const unsigned long long*)&sv[r][q0 + 2];
            const unsigned long long d2 = dup_f32x2(inv2);
            unsigned long long gb[2];
            gb[0] = mul_f32x2(qqp[0], d2);
            gb[1] = mul_f32x2(qqp[1], d2);
            unsigned long long da[4];
#pragma unroll
            for (int i = 0; i < 4; ++i) da[i] = dup_f32x2(qp[i]);
#pragma unroll
            for (int i = 0; i < 4; ++i) {
                fma_f32x2(aG[i][0], da[i], gb[0]);
                fma_f32x2(aG[i][1], da[i], gb[1]);
                fma_f32x2(aU[i][0], da[i], vvp[0]);
                fma_f32x2(aU[i][1], da[i], vvp[1]);
            }
        }
        __syncthreads();
    }

    float* oG = g_scratch[h][c][0];
    float* oU = g_scratch[h][c][1];
#pragma unroll
    for (int i = 0; i < 4; ++i) {
        float4 vg, vu;
        unpack_f32x2(vg.x, vg.y, aG[i][0]);
        unpack_f32x2(vg.z, vg.w, aG[i][1]);
        unpack_f32x2(vu.x, vu.y, aU[i][0]);
        unpack_f32x2(vu.z, vu.w, aU[i][1]);
        *(float4*)&oG[(p0 + i) * 64 + q0] = vg;
        *(float4*)&oU[(p0 + i) * 64 + q0] = vu;
    }
}

// ---------------------------------------------------------------------------
// Kernel 2: reduce chunk partials — EXACT R5 version.
// ---------------------------------------------------------------------------
__global__ __launch_bounds__(256) void reduce_gram() {
    const int h = blockIdx.y;
    const int e = blockIdx.x * 256 + threadIdx.x;
    float sg = 0.f, su = 0.f;
    for (int c = 0; c < CHUNKS; ++c) {
        sg += g_scratch[h][c][0][e];
        su += g_scratch[h][c][1][e];
    }
    g_G[h][e] = sg;
    g_U[h][e] = su;
}

// ---------------------------------------------------------------------------
// Kernel 3: new_trace = 0.99*(trace - (G/denom)@trace) + 0.1*U/denom
// ---------------------------------------------------------------------------
__global__ __launch_bounds__(256) void combine_trace(const float* __restrict__ trace) {
    const int h = blockIdx.x;
    const int t = threadIdx.x;
    __shared__ float Gs[4096];
    __shared__ float Ts[4096];
#pragma unroll
    for (int j = 0; j < 16; ++j) {
        Gs[t + 256 * j] = g_G[h][t + 256 * j];
        Ts[t + 256 * j] = trace[h * 4096 + t + 256 * j];
    }
    __syncthreads();
    const float invd = 1.0f / DENOM;
#pragma unroll
    for (int j = 0; j < 16; ++j) {
        const int e = t + 256 * j;
        const int p = e >> 6, q = e & 63;
        float acc = 0.f;
#pragma unroll 8
        for (int k = 0; k < 64; ++k)
            acc += Gs[p * 64 + k] * Ts[k * 64 + q];
        g_NT[h][e] = 0.99f * (Ts[e] - acc * invd) + 0.1f * g_U[h][e] * invd;
    }
}

// ---------------------------------------------------------------------------
// Kernel 4: B[n][h*64+p] = sum_q NT[h][p][q] * W[n][h*64+q] -> fp16 (single).
// grid (12, 8), register-tiled 4x4.
// ---------------------------------------------------------------------------
__global__ __launch_bounds__(256) void build_M(const float* __restrict__ W) {
    const int h  = blockIdx.y;
    const int n0 = blockIdx.x * 64;
    const int t  = threadIdx.x;
    __shared__ float Wq[64][72];   // [q][n]
    __shared__ float Nq[64][72];   // [q][p]
#pragma unroll
    for (int j = 0; j < 4; ++j) {
        const int idx = t + j * 256;
        const int row = idx >> 4;
        const int q4  = (idx & 15) * 4;
        float4 wv = *(const float4*)(W + (size_t)(n0 + row) * KDIM + h * 64 + q4);
        Wq[q4 + 0][row] = wv.x; Wq[q4 + 1][row] = wv.y;
        Wq[q4 + 2][row] = wv.z; Wq[q4 + 3][row] = wv.w;
        float4 nv = *(const float4*)(&g_NT[h][row * 64 + q4]);
        Nq[q4 + 0][row] = nv.x; Nq[q4 + 1][row] = nv.y;
        Nq[q4 + 2][row] = nv.z; Nq[q4 + 3][row] = nv.w;
    }
    __syncthreads();
    const int tx = t & 15;     // p block
    const int ty = t >> 4;     // n block
    float acc[4][4];
#pragma unroll
    for (int i = 0; i < 4; ++i)
#pragma unroll
        for (int j = 0; j < 4; ++j) acc[i][j] = 0.f;
#pragma unroll 8
    for (int q = 0; q < 64; ++q) {
        const float4 wv = *(const float4*)&Wq[q][ty * 4];
        const float4 nv = *(const float4*)&Nq[q][tx * 4];
        const float w[4] = {wv.x, wv.y, wv.z, wv.w};
        const float nn[4] = {nv.x, nv.y, nv.z, nv.w};
#pragma unroll
        for (int i = 0; i < 4; ++i)
#pragma unroll
            for (int j = 0; j < 4; ++j)
                acc[i][j] += w[i] * nn[j];
    }
#pragma unroll
    for (int i = 0; i < 4; ++i) {
        const int n = n0 + ty * 4 + i;
#pragma unroll
        for (int j = 0; j < 4; ++j) {
            const int k = h * 64 + tx * 4 + j;
            g_Bhi[(size_t)n * KDIM + k] = __float2half_rn(acc[i][j]);
        }
    }
}

// ---------------------------------------------------------------------------
// Kernel 5: out = (Ahi + Alo) @ Bhi^T via mma.sync fp16 (2-term split,
// 16 K-chunks). BM=BN=128, BK=64, 8 warps (2x4), double-buffered cp.async.
// ---------------------------------------------------------------------------
#define STG_BYTES 36864                         // (128*72 + 128*72) * 2B
#define GEMM_SMEM (2 * STG_BYTES)               // 73728

__global__ __launch_bounds__(256, 2) void out_gemm_mma(float* __restrict__ out) {
    extern __shared__ __align__(16) char smem[];
    const int t = threadIdx.x;
    const int n_base = blockIdx.x * 128;
    const int m_base = blockIdx.y * 128;
    const uint32_t sbase = smem_to_u32(smem);

    const int lrow = t >> 3;        // 0..31 base row for loads (x4 iters)
    const int lc8  = t & 7;         // 16B chunk within 64-col row

    // chunk kc in 0..15:  k0 = (kc/2)*64 ; term = kc%2 (0: Ahi, 1: Alo); B = Bhi
    auto load_stage = [&](int kc, int stage) {
        const int k0 = (kc >> 1) * 64;
        const __half* Ag = ((kc & 1) ? g_Alo : g_Ahi);
        const uint32_t sa = sbase + stage * STG_BYTES;
        const uint32_t sb = sa + 128 * 144;
#pragma unroll
        for (int i = 0; i < 4; ++i) {
            const int row = lrow + i * 32;
            const __half* g = Ag + (((size_t)(m_base + row)) << 9) + k0 + lc8 * 8;
            CP_ASYNC_16(sa + row * 144 + lc8 * 16, g);
        }
#pragma unroll
        for (int i = 0; i < 4; ++i) {
            const int row = lrow + i * 32;
            const __half* g = g_Bhi + (((size_t)(n_base + row)) << 9) + k0 + lc8 * 8;
            CP_ASYNC_16(sb + row * 144 + lc8 * 16, g);
        }
        CP_ASYNC_COMMIT();
    };

    const int wid = t >> 5, lane = t & 31;
    const int wm = wid >> 2;        // 0..1  (64 m-rows)
    const int wn = wid & 3;         // 0..3  (32 n-cols)
    const int fr = lane >> 2;       // 0..7
    const int fcb = (lane & 3) * 4; // k byte offset (2 fp16)

    float acc[4][4][4];
#pragma unroll
    for (int mi = 0; mi < 4; ++mi)
#pragma unroll
        for (int ni = 0; ni < 4; ++ni)
#pragma unroll
            for (int j = 0; j < 4; ++j) acc[mi][ni][j] = 0.f;

    load_stage(0, 0);
    for (int kc = 0; kc < 16; ++kc) {
        if (kc + 1 < 16) {
            load_stage(kc + 1, (kc + 1) & 1);
            CP_ASYNC_WAIT(1);
        } else {
            CP_ASYNC_WAIT(0);
        }
        __syncthreads();

        const char* As = smem + (kc & 1) * STG_BYTES;
        const char* Bs = As + 128 * 144;
#pragma unroll
        for (int kk = 0; kk < 4; ++kk) {
            const int cb = kk * 32 + fcb;        // k16-step byte offset
            uint32_t a[4][4];
#pragma unroll
            for (int mi = 0; mi < 4; ++mi) {
                const int r = wm * 64 + mi * 16 + fr;
                a[mi][0] = *(const uint32_t*)(As + r * 144 + cb);
                a[mi][1] = *(const uint32_t*)(As + (r + 8) * 144 + cb);
                a[mi][2] = *(const uint32_t*)(As + r * 144 + cb + 16);
                a[mi][3] = *(const uint32_t*)(As + (r + 8) * 144 + cb + 16);
            }
            uint32_t b[4][2];
#pragma unroll
            for (int ni = 0; ni < 4; ++ni) {
                const int n = wn * 32 + ni * 8 + fr;
                b[ni][0] = *(const uint32_t*)(Bs + n * 144 + cb);
                b[ni][1] = *(const uint32_t*)(Bs + n * 144 + cb + 16);
            }
#pragma unroll
            for (int mi = 0; mi < 4; ++mi)
#pragma unroll
                for (int ni = 0; ni < 4; ++ni)
                    mma_16816_f16(acc[mi][ni], a[mi], b[ni]);
        }
        __syncthreads();
    }

    // Epilogue: c0,c1 -> (r, c..c+1); c2,c3 -> (r+8, c..c+1)
#pragma unroll
    for (int mi = 0; mi < 4; ++mi) {
        const int r = m_base + wm * 64 + mi * 16 + fr;
#pragma unroll
        for (int ni = 0; ni < 4; ++ni) {
            const int cg = n_base + wn * 32 + ni * 8 + (lane & 3) * 2;
            *(float2*)(out + (size_t)r * DM_ + cg) =
                make_float2(acc[mi][ni][0], acc[mi][ni][1]);
            *(float2*)(out + (size_t)(r + 8) * DM_ + cg) =
                make_float2(acc[mi][ni][2], acc[mi][ni][3]);
        }
    }
}

// ---------------------------------------------------------------------------
extern "C" void kernel_launch(void* const* d_in, const int* in_sizes, int n_in,
                              void* d_out, int out_size) {
    const float* Q     = (const float*)d_in[0];
    const float* V     = (const float*)d_in[1];
    const float* trace = (const float*)d_in[2];
    const float* W     = (const float*)d_in[3];
    float* out = (float*)d_out;

    static bool attr_set = false;
    if (!attr_set) {
        cudaFuncSetAttribute(out_gemm_mma, cudaFuncAttributeMaxDynamicSharedMemorySize, GEMM_SMEM);
        attr_set = true;
    }

    prepA<<<(B_ * H_ * (S_ - 1) * 16) / 256, 256>>>(Q);
    zeroA<<<(B_ * KDIM) / 256, 256>>>();
    gram_partial<<<dim3(CHUNKS, H_), 256>>>(Q, V);
    reduce_gram<<<dim3(16, H_), 256>>>();
    combine_trace<<<H_, 256>>>(trace);
    build_M<<<dim3(12, H_), 256>>>(W);
    out_gemm_mma<<<dim3(DM_ / 128, MROWS / 128), 256, GEMM_SMEM>>>(out);
}

// round 8
// speedup vs baseline: 1.7727x; 1.2717x over previous
#include <cuda_runtime.h>
#include <cuda_fp16.h>
#include <cstdint>

// Problem constants
#define B_   8
#define H_   8
#define S_   4096
#define D_   64
#define DM_  768
#define SM2  (S_ - 2)            // 4094
#define ROWS_TOTAL (B_ * SM2)    // 32752
#define CHUNKS 64
#define ROWS_PER_CHUNK 512
#define DENOM ((float)(B_ * SM2))

#define MROWS (B_ * S_)          // 32768
#define KDIM  (H_ * D_)          // 512

// ---------------------------------------------------------------------------
// Static device scratch (allocation-free per harness rules)
// ---------------------------------------------------------------------------
__device__ float g_scratch[H_][CHUNKS][2][D_ * D_];
__device__ float g_G[H_][D_ * D_];
__device__ float g_U[H_][D_ * D_];
__device__ float g_NT[H_][D_ * D_];
__device__ __align__(16) __half g_Ahi[(size_t)MROWS * KDIM];
__device__ __align__(16) __half g_Bhi[(size_t)DM_ * KDIM];

// ---------------------------------------------------------------------------
// Helpers
// ---------------------------------------------------------------------------
__device__ __forceinline__ uint32_t smem_to_u32(const void* p) {
    uint32_t a;
    asm("{ .reg .u64 t; cvta.to.shared.u64 t, %1; cvt.u32.u64 %0, t; }" : "=r"(a) : "l"(p));
    return a;
}
__device__ __forceinline__ unsigned long long dup_f32x2(float x) {
    unsigned long long r;
    asm("mov.b64 %0, {%1, %1};" : "=l"(r) : "r"(__float_as_uint(x)));
    return r;
}
__device__ __forceinline__ void fma_f32x2(unsigned long long& d, unsigned long long a, unsigned long long b) {
    asm("fma.rn.f32x2 %0, %1, %2, %0;" : "+l"(d) : "l"(a), "l"(b));
}
__device__ __forceinline__ unsigned long long mul_f32x2(unsigned long long a, unsigned long long b) {
    unsigned long long r;
    asm("mul.rn.f32x2 %0, %1, %2;" : "=l"(r) : "l"(a), "l"(b));
    return r;
}
__device__ __forceinline__ void unpack_f32x2(float& lo, float& hi, unsigned long long v) {
    uint32_t l, h;
    asm("mov.b64 {%0, %1}, %2;" : "=r"(l), "=r"(h) : "l"(v));
    lo = __uint_as_float(l); hi = __uint_as_float(h);
}
__device__ __forceinline__ void mma_16816_f16(float* c, const uint32_t* a, const uint32_t* b) {
    asm volatile(
        "mma.sync.aligned.m16n8k16.row.col.f32.f16.f16.f32 "
        "{%0,%1,%2,%3}, {%4,%5,%6,%7}, {%8,%9}, {%0,%1,%2,%3};"
        : "+f"(c[0]), "+f"(c[1]), "+f"(c[2]), "+f"(c[3])
        : "r"(a[0]), "r"(a[1]), "r"(a[2]), "r"(a[3]), "r"(b[0]), "r"(b[1]));
}
#define CP_ASYNC_16(smem_u32, gptr) \
    asm volatile("cp.async.cg.shared.global [%0], [%1], 16;" :: "r"(smem_u32), "l"(gptr))
#define CP_ASYNC_COMMIT() asm volatile("cp.async.commit_group;")
#define CP_ASYNC_WAIT(n)  asm volatile("cp.async.wait_group %0;" :: "n"(n))

// ---------------------------------------------------------------------------
// Kernel A1: Qaddr (shift-by-1) -> fp16 A matrix [m][k] (single precision term)
// ---------------------------------------------------------------------------
__global__ __launch_bounds__(256) void prepA(const float* __restrict__ Q) {
    const int idx = blockIdx.x * 256 + threadIdx.x;     // < 8*8*4095*16
    const int c4  = idx & 15;
    const int rst = idx >> 4;
    const int s   = rst % (S_ - 1);                     // 0..4094
    const int bh  = rst / (S_ - 1);
    const int h   = bh & 7;
    const int b   = bh >> 3;
    const float4 v = *(const float4*)(Q + (((size_t)(b * H_ + h)) * S_ + s) * D_ + c4 * 4);
    const size_t m = (size_t)b * S_ + s + 1;
    const size_t o = m * KDIM + h * 64 + c4 * 4;
    *(__half2*)(g_Ahi + o)     = __halves2half2(__float2half_rn(v.x), __float2half_rn(v.y));
    *(__half2*)(g_Ahi + o + 2) = __halves2half2(__float2half_rn(v.z), __float2half_rn(v.w));
}

__global__ __launch_bounds__(256) void zeroA() {
    const int idx = blockIdx.x * 256 + threadIdx.x;     // < 8*512
    const int b = idx >> 9, col = idx & 511;
    const size_t o = (size_t)b * S_ * KDIM + col;
    g_Ahi[o] = __float2half(0.f);
}

// ---------------------------------------------------------------------------
// Kernel 1: per-(head, chunk) partial Gram sums. Inner body identical to the
// proven R5 version; row tile widened 8 -> 16 to halve __syncthreads count.
// ---------------------------------------------------------------------------
__global__ __launch_bounds__(256) void gram_partial(const float* __restrict__ Q,
                                                    const float* __restrict__ V) {
    const int c = blockIdx.x;
    const int h = blockIdx.y;
    const int t = threadIdx.x;

    __shared__ float sq[16][64];
    __shared__ float sv[16][64];
    __shared__ float sinv[16];

    const int p0 = (t >> 4) * 4;
    const int q0 = (t & 15) * 4;

    unsigned long long aG[4][2], aU[4][2];
#pragma unroll
    for (int i = 0; i < 4; ++i) { aG[i][0] = aG[i][1] = 0ull; aU[i][0] = aU[i][1] = 0ull; }

    const int rbase = c * ROWS_PER_CHUNK;
    const int which = t >> 7;
    const int li    = t & 127;
    const int lrow  = li >> 4;       // 0..7
    const int lf4   = li & 15;       // 0..15

    for (int it = 0; it < ROWS_PER_CHUNK / 16; ++it) {  // 32 iterations
        const int r16 = rbase + it * 16;
        // --- load 16 q-rows + 16 v-rows ---
#pragma unroll
        for (int half = 0; half < 2; ++half) {
            const int row = lrow + half * 8;
            const int r = r16 + row;
            float4 val = make_float4(0.f, 0.f, 0.f, 0.f);
            if (r < ROWS_TOTAL) {
                const int b = r / SM2;
                const int i = r - b * SM2;
                if (which == 0)
                    val = *(const float4*)(Q + (((size_t)(b * H_ + h)) * S_ + i) * D_ + lf4 * 4);
                else
                    val = *(const float4*)(V + (((size_t)(b * H_ + h)) * S_ + (i + 2)) * D_ + lf4 * 4);
            }
            float* dst = (which == 0) ? &sq[row][lf4 * 4] : &sv[row][lf4 * 4];
            *(float4*)dst = val;
        }
        __syncthreads();
        // --- inverse norms: warp w handles rows w and w+8 ---
        {
            const int w = t >> 5, lane = t & 31;
#pragma unroll
            for (int half = 0; half < 2; ++half) {
                const int row = w + half * 8;
                float e0 = sq[row][lane], e1 = sq[row][lane + 32];
                float ss = e0 * e0 + e1 * e1;
#pragma unroll
                for (int off = 16; off > 0; off >>= 1)
                    ss += __shfl_xor_sync(0xffffffffu, ss, off);
                if (lane == 0) sinv[row] = 1.0f / fmaxf(sqrtf(ss), 1e-8f);
            }
        }
        __syncthreads();
        // --- accumulate 16 rows (body identical to R5) ---
#pragma unroll 4
        for (int r = 0; r < 16; ++r) {
            const float inv  = sinv[r];
            const float inv2 = inv * inv;
            float qp[4];
#pragma unroll
            for (int i = 0; i < 4; ++i) qp[i] = sq[r][p0 + i];
            unsigned long long qqp[2], vvp[2];
            qqp[0] = *(const unsigned long long*)&sq[r][q0];
            qqp[1] = *(const unsigned long long*)&sq[r][q0 + 2];
            vvp[0] = *(const unsigned long long*)&sv[r][q0];
            vvp[1] = *(const unsigned long long*)&sv[r][q0 + 2];
            const unsigned long long d2 = dup_f32x2(inv2);
            unsigned long long gb[2];
            gb[0] = mul_f32x2(qqp[0], d2);
            gb[1] = mul_f32x2(qqp[1], d2);
            unsigned long long da[4];
#pragma unroll
            for (int i = 0; i < 4; ++i) da[i] = dup_f32x2(qp[i]);
#pragma unroll
            for (int i = 0; i < 4; ++i) {
                fma_f32x2(aG[i][0], da[i], gb[0]);
                fma_f32x2(aG[i][1], da[i], gb[1]);
                fma_f32x2(aU[i][0], da[i], vvp[0]);
                fma_f32x2(aU[i][1], da[i], vvp[1]);
            }
        }
        __syncthreads();
    }

    float* oG = g_scratch[h][c][0];
    float* oU = g_scratch[h][c][1];
#pragma unroll
    for (int i = 0; i < 4; ++i) {
        float4 vg, vu;
        unpack_f32x2(vg.x, vg.y, aG[i][0]);
        unpack_f32x2(vg.z, vg.w, aG[i][1]);
        unpack_f32x2(vu.x, vu.y, aU[i][0]);
        unpack_f32x2(vu.z, vu.w, aU[i][1]);
        *(float4*)&oG[(p0 + i) * 64 + q0] = vg;
        *(float4*)&oU[(p0 + i) * 64 + q0] = vu;
    }
}

// ---------------------------------------------------------------------------
// Kernel 2: reduce chunk partials — EXACT R5 version.
// ---------------------------------------------------------------------------
__global__ __launch_bounds__(256) void reduce_gram() {
    const int h = blockIdx.y;
    const int e = blockIdx.x * 256 + threadIdx.x;
    float sg = 0.f, su = 0.f;
    for (int c = 0; c < CHUNKS; ++c) {
        sg += g_scratch[h][c][0][e];
        su += g_scratch[h][c][1][e];
    }
    g_G[h][e] = sg;
    g_U[h][e] = su;
}

// ---------------------------------------------------------------------------
// Kernel 3: new_trace = 0.99*(trace - (G/denom)@trace) + 0.1*U/denom
// ---------------------------------------------------------------------------
__global__ __launch_bounds__(256) void combine_trace(const float* __restrict__ trace) {
    const int h = blockIdx.x;
    const int t = threadIdx.x;
    __shared__ float Gs[4096];
    __shared__ float Ts[4096];
#pragma unroll
    for (int j = 0; j < 16; ++j) {
        Gs[t + 256 * j] = g_G[h][t + 256 * j];
        Ts[t + 256 * j] = trace[h * 4096 + t + 256 * j];
    }
    __syncthreads();
    const float invd = 1.0f / DENOM;
#pragma unroll
    for (int j = 0; j < 16; ++j) {
        const int e = t + 256 * j;
        const int p = e >> 6, q = e & 63;
        float acc = 0.f;
#pragma unroll 8
        for (int k = 0; k < 64; ++k)
            acc += Gs[p * 64 + k] * Ts[k * 64 + q];
        g_NT[h][e] = 0.99f * (Ts[e] - acc * invd) + 0.1f * g_U[h][e] * invd;
    }
}

// ---------------------------------------------------------------------------
// Kernel 4: B[n][h*64+p] = sum_q NT[h][p][q] * W[n][h*64+q] -> fp16.
// grid (12, 8), register-tiled 4x4.
// ---------------------------------------------------------------------------
__global__ __launch_bounds__(256) void build_M(const float* __restrict__ W) {
    const int h  = blockIdx.y;
    const int n0 = blockIdx.x * 64;
    const int t  = threadIdx.x;
    __shared__ float Wq[64][72];   // [q][n]
    __shared__ float Nq[64][72];   // [q][p]
#pragma unroll
    for (int j = 0; j < 4; ++j) {
        const int idx = t + j * 256;
        const int row = idx >> 4;
        const int q4  = (idx & 15) * 4;
        float4 wv = *(const float4*)(W + (size_t)(n0 + row) * KDIM + h * 64 + q4);
        Wq[q4 + 0][row] = wv.x; Wq[q4 + 1][row] = wv.y;
        Wq[q4 + 2][row] = wv.z; Wq[q4 + 3][row] = wv.w;
        float4 nv = *(const float4*)(&g_NT[h][row * 64 + q4]);
        Nq[q4 + 0][row] = nv.x; Nq[q4 + 1][row] = nv.y;
        Nq[q4 + 2][row] = nv.z; Nq[q4 + 3][row] = nv.w;
    }
    __syncthreads();
    const int tx = t & 15;     // p block
    const int ty = t >> 4;     // n block
    float acc[4][4];
#pragma unroll
    for (int i = 0; i < 4; ++i)
#pragma unroll
        for (int j = 0; j < 4; ++j) acc[i][j] = 0.f;
#pragma unroll 8
    for (int q = 0; q < 64; ++q) {
        const float4 wv = *(const float4*)&Wq[q][ty * 4];
        const float4 nv = *(const float4*)&Nq[q][tx * 4];
        const float w[4] = {wv.x, wv.y, wv.z, wv.w};
        const float nn[4] = {nv.x, nv.y, nv.z, nv.w};
#pragma unroll
        for (int i = 0; i < 4; ++i)
#pragma unroll
            for (int j = 0; j < 4; ++j)
                acc[i][j] += w[i] * nn[j];
    }
#pragma unroll
    for (int i = 0; i < 4; ++i) {
        const int n = n0 + ty * 4 + i;
#pragma unroll
        for (int j = 0; j < 4; ++j) {
            const int k = h * 64 + tx * 4 + j;
            g_Bhi[(size_t)n * KDIM + k] = __float2half_rn(acc[i][j]);
        }
    }
}

// ---------------------------------------------------------------------------
// Kernel 5: out = Ahi @ Bhi^T via mma.sync fp16 (single term, 8 K-chunks).
// BM=BN=128, BK=64, 8 warps (2x4), double-buffered cp.async.
// ---------------------------------------------------------------------------
#define STG_BYTES 36864                         // (128*72 + 128*72) * 2B
#define GEMM_SMEM (2 * STG_BYTES)               // 73728

__global__ __launch_bounds__(256, 2) void out_gemm_mma(float* __restrict__ out) {
    extern __shared__ __align__(16) char smem[];
    const int t = threadIdx.x;
    const int n_base = blockIdx.x * 128;
    const int m_base = blockIdx.y * 128;
    const uint32_t sbase = smem_to_u32(smem);

    const int lrow = t >> 3;        // 0..31 base row for loads (x4 iters)
    const int lc8  = t & 7;         // 16B chunk within 64-col row

    // chunk kc in 0..7:  k0 = kc*64
    auto load_stage = [&](int kc, int stage) {
        const int k0 = kc * 64;
        const uint32_t sa = sbase + stage * STG_BYTES;
        const uint32_t sb = sa + 128 * 144;
#pragma unroll
        for (int i = 0; i < 4; ++i) {
            const int row = lrow + i * 32;
            const __half* g = g_Ahi + (((size_t)(m_base + row)) << 9) + k0 + lc8 * 8;
            CP_ASYNC_16(sa + row * 144 + lc8 * 16, g);
        }
#pragma unroll
        for (int i = 0; i < 4; ++i) {
            const int row = lrow + i * 32;
            const __half* g = g_Bhi + (((size_t)(n_base + row)) << 9) + k0 + lc8 * 8;
            CP_ASYNC_16(sb + row * 144 + lc8 * 16, g);
        }
        CP_ASYNC_COMMIT();
    };

    const int wid = t >> 5, lane = t & 31;
    const int wm = wid >> 2;        // 0..1  (64 m-rows)
    const int wn = wid & 3;         // 0..3  (32 n-cols)
    const int fr = lane >> 2;       // 0..7
    const int fcb = (lane & 3) * 4; // k byte offset (2 fp16)

    float acc[4][4][4];
#pragma unroll
    for (int mi = 0; mi < 4; ++mi)
#pragma unroll
        for (int ni = 0; ni < 4; ++ni)
#pragma unroll
            for (int j = 0; j < 4; ++j) acc[mi][ni][j] = 0.f;

    load_stage(0, 0);
    for (int kc = 0; kc < 8; ++kc) {
        if (kc + 1 < 8) {
            load_stage(kc + 1, (kc + 1) & 1);
            CP_ASYNC_WAIT(1);
        } else {
            CP_ASYNC_WAIT(0);
        }
        __syncthreads();

        const char* As = smem + (kc & 1) * STG_BYTES;
        const char* Bs = As + 128 * 144;
#pragma unroll
        for (int kk = 0; kk < 4; ++kk) {
            const int cb = kk * 32 + fcb;        // k16-step byte offset
            uint32_t a[4][4];
#pragma unroll
            for (int mi = 0; mi < 4; ++mi) {
                const int r = wm * 64 + mi * 16 + fr;
                a[mi][0] = *(const uint32_t*)(As + r * 144 + cb);
                a[mi][1] = *(const uint32_t*)(As + (r + 8) * 144 + cb);
                a[mi][2] = *(const uint32_t*)(As + r * 144 + cb + 16);
                a[mi][3] = *(const uint32_t*)(As + (r + 8) * 144 + cb + 16);
            }
            uint32_t b[4][2];
#pragma unroll
            for (int ni = 0; ni < 4; ++ni) {
                const int n = wn * 32 + ni * 8 + fr;
                b[ni][0] = *(const uint32_t*)(Bs + n * 144 + cb);
                b[ni][1] = *(const uint32_t*)(Bs + n * 144 + cb + 16);
            }
#pragma unroll
            for (int mi = 0; mi < 4; ++mi)
#pragma unroll
                for (int ni = 0; ni < 4; ++ni)
                    mma_16816_f16(acc[mi][ni], a[mi], b[ni]);
        }
        __syncthreads();
    }

    // Epilogue: c0,c1 -> (r, c..c+1); c2,c3 -> (r+8, c..c+1)
#pragma unroll
    for (int mi = 0; mi < 4; ++mi) {
        const int r = m_base + wm * 64 + mi * 16 + fr;
#pragma unroll
        for (int ni = 0; ni < 4; ++ni) {
            const int cg = n_base + wn * 32 + ni * 8 + (lane & 3) * 2;
            *(float2*)(out + (size_t)r * DM_ + cg) =
                make_float2(acc[mi][ni][0], acc[mi][ni][1]);
            *(float2*)(out + (size_t)(r + 8) * DM_ + cg) =
                make_float2(acc[mi][ni][2], acc[mi][ni][3]);
        }
    }
}

// ---------------------------------------------------------------------------
extern "C" void kernel_launch(void* const* d_in, const int* in_sizes, int n_in,
                              void* d_out, int out_size) {
    const float* Q     = (const float*)d_in[0];
    const float* V     = (const float*)d_in[1];
    const float* trace = (const float*)d_in[2];
    const float* W     = (const float*)d_in[3];
    float* out = (float*)d_out;

    static bool attr_set = false;
    if (!attr_set) {
        cudaFuncSetAttribute(out_gemm_mma, cudaFuncAttributeMaxDynamicSharedMemorySize, GEMM_SMEM);
        attr_set = true;
    }

    prepA<<<(B_ * H_ * (S_ - 1) * 16) / 256, 256>>>(Q);
    zeroA<<<(B_ * KDIM) / 256, 256>>>();
    gram_partial<<<dim3(CHUNKS, H_), 256>>>(Q, V);
    reduce_gram<<<dim3(16, H_), 256>>>();
    combine_trace<<<H_, 256>>>(trace);
    build_M<<<dim3(12, H_), 256>>>(W);
    out_gemm_mma<<<dim3(DM_ / 128, MROWS / 128), 256, GEMM_SMEM>>>(out);
}

// round 11
// speedup vs baseline: 3.1245x; 1.7626x over previous
#include <cuda_runtime.h>
#include <cuda_fp16.h>
#include <cstdint>

// Problem constants
#define B_   8
#define H_   8
#define S_   4096
#define D_   64
#define DM_  768
#define SM2  (S_ - 2)            // 4094
#define ROWS_TOTAL (B_ * SM2)    // 32752
#define CHUNKS 64
#define ROWS_PER_CHUNK 512
#define DENOM ((float)(B_ * SM2))

#define MROWS (B_ * S_)          // 32768
#define KDIM  (H_ * D_)          // 512

// ---------------------------------------------------------------------------
// Static device scratch (allocation-free per harness rules)
// ---------------------------------------------------------------------------
__device__ float g_scratch[H_][CHUNKS][2][D_ * D_];
__device__ float g_G[H_][D_ * D_];
__device__ float g_U[H_][D_ * D_];
__device__ float g_NT[H_][D_ * D_];
__device__ __align__(16) __half g_Ahi[(size_t)MROWS * KDIM];
__device__ __align__(16) __half g_Bhi[(size_t)DM_ * KDIM];

// ---------------------------------------------------------------------------
// Helpers
// ---------------------------------------------------------------------------
__device__ __forceinline__ uint32_t smem_to_u32(const void* p) {
    uint32_t a;
    asm("{ .reg .u64 t; cvta.to.shared.u64 t, %1; cvt.u32.u64 %0, t; }" : "=r"(a) : "l"(p));
    return a;
}
__device__ __forceinline__ void mma_16816_f16(float* c, const uint32_t* a, const uint32_t* b) {
    asm volatile(
        "mma.sync.aligned.m16n8k16.row.col.f32.f16.f16.f32 "
        "{%0,%1,%2,%3}, {%4,%5,%6,%7}, {%8,%9}, {%0,%1,%2,%3};"
        : "+f"(c[0]), "+f"(c[1]), "+f"(c[2]), "+f"(c[3])
        : "r"(a[0]), "r"(a[1]), "r"(a[2]), "r"(a[3]), "r"(b[0]), "r"(b[1]));
}
__device__ __forceinline__ void ldsm_x4_trans(uint32_t& r0, uint32_t& r1,
                                              uint32_t& r2, uint32_t& r3, uint32_t addr) {
    asm volatile("ldmatrix.sync.aligned.m8n8.x4.trans.shared.b16 {%0,%1,%2,%3}, [%4];"
                 : "=r"(r0), "=r"(r1), "=r"(r2), "=r"(r3) : "r"(addr));
}
#define CP_ASYNC_16(smem_u32, gptr) \
    asm volatile("cp.async.cg.shared.global [%0], [%1], 16;" :: "r"(smem_u32), "l"(gptr))
#define CP_ASYNC_COMMIT() asm volatile("cp.async.commit_group;")
#define CP_ASYNC_WAIT(n)  asm volatile("cp.async.wait_group %0;" :: "n"(n))

// ---------------------------------------------------------------------------
// Kernel A1: Qaddr (shift-by-1) -> fp16 A matrix [m][k]
// ---------------------------------------------------------------------------
__global__ __launch_bounds__(256) void prepA(const float* __restrict__ Q) {
    const int idx = blockIdx.x * 256 + threadIdx.x;     // < 8*8*4095*16
    const int c4  = idx & 15;
    const int rst = idx >> 4;
    const int s   = rst % (S_ - 1);                     // 0..4094
    const int bh  = rst / (S_ - 1);
    const int h   = bh & 7;
    const int b   = bh >> 3;
    const float4 v = *(const float4*)(Q + (((size_t)(b * H_ + h)) * S_ + s) * D_ + c4 * 4);
    const size_t m = (size_t)b * S_ + s + 1;
    const size_t o = m * KDIM + h * 64 + c4 * 4;
    *(__half2*)(g_Ahi + o)     = __halves2half2(__float2half_rn(v.x), __float2half_rn(v.y));
    *(__half2*)(g_Ahi + o + 2) = __halves2half2(__float2half_rn(v.z), __float2half_rn(v.w));
}

__global__ __launch_bounds__(256) void zeroA() {
    const int idx = blockIdx.x * 256 + threadIdx.x;     // < 8*512
    const int b = idx >> 9, col = idx & 511;
    const size_t o = (size_t)b * S_ * KDIM + col;
    g_Ahi[o] = __float2half(0.f);
}

// ---------------------------------------------------------------------------
// Kernel 1: per-(head, chunk) partial Gram sums via tensor cores.
//   G[h] += Q̂ᵀQ̂ ; U[h] += QᵀV_shift. 64-row stages: f32 loads -> norms ->
//   fp16 k-major smem tiles -> ldmatrix.trans fragments -> mma.sync.
//   Warps 0-3 compute G rows 16w..16w+15 (n=0..63); warps 4-7 same for U.
// ---------------------------------------------------------------------------
#define RT 64       // rows per stage
#define RP 72       // padded halfs per smem row (36 words; 36 mod 32 = 4)

__global__ __launch_bounds__(256, 2) void gram_mma(const float* __restrict__ Q,
                                                   const float* __restrict__ V) {
    const int c = blockIdx.x;   // chunk (512 rows)
    const int h = blockIdx.y;
    const int t = threadIdx.x;
    const int wid = t >> 5, lane = t & 31;

    __shared__ __half Tqh[RT * RP];   // q_hat, k-major: [r][d]
    __shared__ __half Tq [RT * RP];   // q
    __shared__ __half Tv [RT * RP];   // v (shift+2)

    const uint32_t sTqh = smem_to_u32(Tqh);
    const uint32_t sTq  = smem_to_u32(Tq);
    const uint32_t sTv  = smem_to_u32(Tv);

    // load mapping: thread covers row r = t>>2, col quarter tq = t&3 (16 cols)
    const int lr = t >> 2;
    const int tq = t & 3;

    // mma mapping
    const int p0 = 16 * (wid & 3);
    const uint32_t TA = (wid < 4) ? sTqh : sTq;
    const uint32_t TB = (wid < 4) ? sTqh : sTv;
    const int l8  = lane & 7;
    const int sub = lane >> 3;
    // a-frag: matrix row k0 + (sub>>1)*8 + l8, col p0 + (sub&1)*8
    const uint32_t a_off = (uint32_t)((((sub >> 1) * 8 + l8) * RP + p0 + (sub & 1) * 8) * 2);
    // b-frag pair: matrix row k0 + (sub&1)*8 + l8, col nt*8 + (sub>>1)*8
    const uint32_t b_off = (uint32_t)((((sub & 1) * 8 + l8) * RP + (sub >> 1) * 8) * 2);

    float acc[8][4];
#pragma unroll
    for (int i = 0; i < 8; ++i)
#pragma unroll
        for (int j = 0; j < 4; ++j) acc[i][j] = 0.f;

    for (int st = 0; st < ROWS_PER_CHUNK / RT; ++st) {   // 8 stages
        const int gr = c * ROWS_PER_CHUNK + st * RT + lr;
        float q[16], v[16];
#pragma unroll
        for (int i = 0; i < 16; ++i) { q[i] = 0.f; v[i] = 0.f; }
        if (gr < ROWS_TOTAL) {
            const int b = gr / SM2;
            const int i = gr - b * SM2;
            const float* qrow = Q + (((size_t)(b * H_ + h)) * S_ + i) * D_ + tq * 16;
            const float* vrow = V + (((size_t)(b * H_ + h)) * S_ + i + 2) * D_ + tq * 16;
#pragma unroll
            for (int j = 0; j < 4; ++j) {
                *(float4*)&q[j * 4] = *(const float4*)(qrow + j * 4);
                *(float4*)&v[j * 4] = *(const float4*)(vrow + j * 4);
            }
        }
        // row norm: reduce over the 4 lanes covering this row (lane bits 0-1)
        float ss = 0.f;
#pragma unroll
        for (int i = 0; i < 16; ++i) ss += q[i] * q[i];
        ss += __shfl_xor_sync(0xffffffffu, ss, 1);
        ss += __shfl_xor_sync(0xffffffffu, ss, 2);
        const float inv = 1.0f / fmaxf(sqrtf(ss), 1e-8f);

        __half2 hqh[8], hq[8], hv[8];
#pragma unroll
        for (int i = 0; i < 8; ++i) {
            hqh[i] = __floats2half2_rn(q[2 * i] * inv, q[2 * i + 1] * inv);
            hq[i]  = __floats2half2_rn(q[2 * i], q[2 * i + 1]);
            hv[i]  = __floats2half2_rn(v[2 * i], v[2 * i + 1]);
        }
        __syncthreads();   // previous stage's mma reads done
        {
            __half* d0 = Tqh + lr * RP + tq * 16;
            *(uint4*)(d0)     = *(uint4*)&hqh[0];
            *(uint4*)(d0 + 8) = *(uint4*)&hqh[4];
            __half* d1 = Tq + lr * RP + tq * 16;
            *(uint4*)(d1)     = *(uint4*)&hq[0];
            *(uint4*)(d1 + 8) = *(uint4*)&hq[4];
            __half* d2 = Tv + lr * RP + tq * 16;
            *(uint4*)(d2)     = *(uint4*)&hv[0];
            *(uint4*)(d2 + 8) = *(uint4*)&hv[4];
        }
        __syncthreads();

#pragma unroll
        for (int ks = 0; ks < RT / 16; ++ks) {           // 4 k16-steps
            const uint32_t kb = (uint32_t)(ks * 16 * RP * 2);
            uint32_t a[4];
            ldsm_x4_trans(a[0], a[1], a[2], a[3], TA + kb + a_off);
#pragma unroll
            for (int nt = 0; nt < 8; nt += 2) {
                uint32_t b0, b1, b2, b3;
                ldsm_x4_trans(b0, b1, b2, b3, TB + kb + b_off + nt * 8 * 2);
                uint32_t bb0[2] = {b0, b1};
                uint32_t bb1[2] = {b2, b3};
                mma_16816_f16(acc[nt],     a, bb0);
                mma_16816_f16(acc[nt + 1], a, bb1);
            }
        }
    }

    // write partials
    float* o = g_scratch[h][c][(wid < 4) ? 0 : 1];
    const int fr = lane >> 2;
    const int c2 = (lane & 3) * 2;
#pragma unroll
    for (int nt = 0; nt < 8; ++nt) {
        const int col = nt * 8 + c2;
        *(float2*)&o[(p0 + fr) * 64 + col]     = make_float2(acc[nt][0], acc[nt][1]);
        *(float2*)&o[(p0 + fr + 8) * 64 + col] = make_float2(acc[nt][2], acc[nt][3]);
    }
}

// ---------------------------------------------------------------------------
// Kernel 2: reduce chunk partials — EXACT R5 version.
// ---------------------------------------------------------------------------
__global__ __launch_bounds__(256) void reduce_gram() {
    const int h = blockIdx.y;
    const int e = blockIdx.x * 256 + threadIdx.x;
    float sg = 0.f, su = 0.f;
    for (int c = 0; c < CHUNKS; ++c) {
        sg += g_scratch[h][c][0][e];
        su += g_scratch[h][c][1][e];
    }
    g_G[h][e] = sg;
    g_U[h][e] = su;
}

// ---------------------------------------------------------------------------
// Kernel 3: new_trace = 0.99*(trace - (G/denom)@trace) + 0.1*U/denom
// ---------------------------------------------------------------------------
__global__ __launch_bounds__(256) void combine_trace(const float* __restrict__ trace) {
    const int h = blockIdx.x;
    const int t = threadIdx.x;
    __shared__ float Gs[4096];
    __shared__ float Ts[4096];
#pragma unroll
    for (int j = 0; j < 16; ++j) {
        Gs[t + 256 * j] = g_G[h][t + 256 * j];
        Ts[t + 256 * j] = trace[h * 4096 + t + 256 * j];
    }
    __syncthreads();
    const float invd = 1.0f / DENOM;
#pragma unroll
    for (int j = 0; j < 16; ++j) {
        const int e = t + 256 * j;
        const int p = e >> 6, q = e & 63;
        float acc = 0.f;
#pragma unroll 8
        for (int k = 0; k < 64; ++k)
            acc += Gs[p * 64 + k] * Ts[k * 64 + q];
        g_NT[h][e] = 0.99f * (Ts[e] - acc * invd) + 0.1f * g_U[h][e] * invd;
    }
}

// ---------------------------------------------------------------------------
// Kernel 4: B[n][h*64+p] = sum_q NT[h][p][q] * W[n][h*64+q] -> fp16.
// ---------------------------------------------------------------------------
__global__ __launch_bounds__(256) void build_M(const float* __restrict__ W) {
    const int h  = blockIdx.y;
    const int n0 = blockIdx.x * 64;
    const int t  = threadIdx.x;
    __shared__ float Wq[64][72];   // [q][n]
    __shared__ float Nq[64][72];   // [q][p]
#pragma unroll
    for (int j = 0; j < 4; ++j) {
        const int idx = t + j * 256;
        const int row = idx >> 4;
        const int q4  = (idx & 15) * 4;
        float4 wv = *(const float4*)(W + (size_t)(n0 + row) * KDIM + h * 64 + q4);
        Wq[q4 + 0][row] = wv.x; Wq[q4 + 1][row] = wv.y;
        Wq[q4 + 2][row] = wv.z; Wq[q4 + 3][row] = wv.w;
        float4 nv = *(const float4*)(&g_NT[h][row * 64 + q4]);
        Nq[q4 + 0][row] = nv.x; Nq[q4 + 1][row] = nv.y;
        Nq[q4 + 2][row] = nv.z; Nq[q4 + 3][row] = nv.w;
    }
    __syncthreads();
    const int tx = t & 15;     // p block
    const int ty = t >> 4;     // n block
    float acc[4][4];
#pragma unroll
    for (int i = 0; i < 4; ++i)
#pragma unroll
        for (int j = 0; j < 4; ++j) acc[i][j] = 0.f;
#pragma unroll 8
    for (int q = 0; q < 64; ++q) {
        const float4 wv = *(const float4*)&Wq[q][ty * 4];
        const float4 nv = *(const float4*)&Nq[q][tx * 4];
        const float w[4] = {wv.x, wv.y, wv.z, wv.w};
        const float nn[4] = {nv.x, nv.y, nv.z, nv.w};
#pragma unroll
        for (int i = 0; i < 4; ++i)
#pragma unroll
            for (int j = 0; j < 4; ++j)
                acc[i][j] += w[i] * nn[j];
    }
#pragma unroll
    for (int i = 0; i < 4; ++i) {
        const int n = n0 + ty * 4 + i;
#pragma unroll
        for (int j = 0; j < 4; ++j) {
            const int k = h * 64 + tx * 4 + j;
            g_Bhi[(size_t)n * KDIM + k] = __float2half_rn(acc[i][j]);
        }
    }
}

// ---------------------------------------------------------------------------
// Kernel 5: out = Ahi @ Bhi^T via mma.sync fp16 (8 K-chunks) — EXACT R8.
// ---------------------------------------------------------------------------
#define STG_BYTES 36864                         // (128*72 + 128*72) * 2B
#define GEMM_SMEM (2 * STG_BYTES)               // 73728

__global__ __launch_bounds__(256, 2) void out_gemm_mma(float* __restrict__ out) {
    extern __shared__ __align__(16) char smem[];
    const int t = threadIdx.x;
    const int n_base = blockIdx.x * 128;
    const int m_base = blockIdx.y * 128;
    const uint32_t sbase = smem_to_u32(smem);

    const int lrow = t >> 3;
    const int lc8  = t & 7;

    auto load_stage = [&](int kc, int stage) {
        const int k0 = kc * 64;
        const uint32_t sa = sbase + stage * STG_BYTES;
        const uint32_t sb = sa + 128 * 144;
#pragma unroll
        for (int i = 0; i < 4; ++i) {
            const int row = lrow + i * 32;
            const __half* g = g_Ahi + (((size_t)(m_base + row)) << 9) + k0 + lc8 * 8;
            CP_ASYNC_16(sa + row * 144 + lc8 * 16, g);
        }
#pragma unroll
        for (int i = 0; i < 4; ++i) {
            const int row = lrow + i * 32;
            const __half* g = g_Bhi + (((size_t)(n_base + row)) << 9) + k0 + lc8 * 8;
            CP_ASYNC_16(sb + row * 144 + lc8 * 16, g);
        }
        CP_ASYNC_COMMIT();
    };

    const int wid = t >> 5, lane = t & 31;
    const int wm = wid >> 2;
    const int wn = wid & 3;
    const int fr = lane >> 2;
    const int fcb = (lane & 3) * 4;

    float acc[4][4][4];
#pragma unroll
    for (int mi = 0; mi < 4; ++mi)
#pragma unroll
        for (int ni = 0; ni < 4; ++ni)
#pragma unroll
            for (int j = 0; j < 4; ++j) acc[mi][ni][j] = 0.f;

    load_stage(0, 0);
    for (int kc = 0; kc < 8; ++kc) {
        if (kc + 1 < 8) {
            load_stage(kc + 1, (kc + 1) & 1);
            CP_ASYNC_WAIT(1);
        } else {
            CP_ASYNC_WAIT(0);
        }
        __syncthreads();

        const char* As = smem + (kc & 1) * STG_BYTES;
        const char* Bs = As + 128 * 144;
#pragma unroll
        for (int kk = 0; kk < 4; ++kk) {
            const int cb = kk * 32 + fcb;
            uint32_t a[4][4];
#pragma unroll
            for (int mi = 0; mi < 4; ++mi) {
                const int r = wm * 64 + mi * 16 + fr;
                a[mi][0] = *(const uint32_t*)(As + r * 144 + cb);
                a[mi][1] = *(const uint32_t*)(As + (r + 8) * 144 + cb);
                a[mi][2] = *(const uint32_t*)(As + r * 144 + cb + 16);
                a[mi][3] = *(const uint32_t*)(As + (r + 8) * 144 + cb + 16);
            }
            uint32_t b[4][2];
#pragma unroll
            for (int ni = 0; ni < 4; ++ni) {
                const int n = wn * 32 + ni * 8 + fr;
                b[ni][0] = *(const uint32_t*)(Bs + n * 144 + cb);
                b[ni][1] = *(const uint32_t*)(Bs + n * 144 + cb + 16);
            }
#pragma unroll
            for (int mi = 0; mi < 4; ++mi)
#pragma unroll
                for (int ni = 0; ni < 4; ++ni)
                    mma_16816_f16(acc[mi][ni], a[mi], b[ni]);
        }
        __syncthreads();
    }

#pragma unroll
    for (int mi = 0; mi < 4; ++mi) {
        const int r = m_base + wm * 64 + mi * 16 + fr;
#pragma unroll
        for (int ni = 0; ni < 4; ++ni) {
            const int cg = n_base + wn * 32 + ni * 8 + (lane & 3) * 2;
            *(float2*)(out + (size_t)r * DM_ + cg) =
                make_float2(acc[mi][ni][0], acc[mi][ni][1]);
            *(float2*)(out + (size_t)(r + 8) * DM_ + cg) =
                make_float2(acc[mi][ni][2], acc[mi][ni][3]);
        }
    }
}

// ---------------------------------------------------------------------------
extern "C" void kernel_launch(void* const* d_in, const int* in_sizes, int n_in,
                              void* d_out, int out_size) {
    const float* Q     = (const float*)d_in[0];
    const float* V     = (const float*)d_in[1];
    const float* trace = (const float*)d_in[2];
    const float* W     = (const float*)d_in[3];
    float* out = (float*)d_out;

    static bool attr_set = false;
    if (!attr_set) {
        cudaFuncSetAttribute(out_gemm_mma, cudaFuncAttributeMaxDynamicSharedMemorySize, GEMM_SMEM);
        attr_set = true;
    }

    prepA<<<(B_ * H_ * (S_ - 1) * 16) / 256, 256>>>(Q);
    zeroA<<<(B_ * KDIM) / 256, 256>>>();
    gram_mma<<<dim3(CHUNKS, H_), 256>>>(Q, V);
    reduce_gram<<<dim3(16, H_), 256>>>();
    combine_trace<<<H_, 256>>>(trace);
    build_M<<<dim3(12, H_), 256>>>(W);
    out_gemm_mma<<<dim3(DM_ / 128, MROWS / 128), 256, GEMM_SMEM>>>(out);
}

// round 12
// speedup vs baseline: 3.3773x; 1.0809x over previous
#include <cuda_runtime.h>
#include <cuda_fp16.h>
#include <cstdint>

// Problem constants
#define B_   8
#define H_   8
#define S_   4096
#define D_   64
#define DM_  768
#define SM2  (S_ - 2)            // 4094 (rows entering the Hebbian update)
#define RPB  (S_ - 1)            // 4095 (rows per batch incl. A-only row i=4094)
#define ROWS_A (B_ * RPB)        // 32760
#define DENOM ((float)(B_ * SM2))

#define GCH   32                 // gram chunks
#define GROWS 1024               // rows per chunk

#define MROWS (B_ * S_)          // 32768
#define KDIM  (H_ * D_)          // 512

// ---------------------------------------------------------------------------
// Static device scratch (allocation-free per harness rules)
// ---------------------------------------------------------------------------
__device__ float g_scratch[H_][GCH][2][D_ * D_];
__device__ float g_G[H_][D_ * D_];
__device__ float g_U[H_][D_ * D_];
__device__ float g_NT[H_][D_ * D_];
__device__ __align__(16) __half g_Ahi[(size_t)MROWS * KDIM];
__device__ __align__(16) __half g_Bhi[(size_t)DM_ * KDIM];

// ---------------------------------------------------------------------------
// Helpers
// ---------------------------------------------------------------------------
__device__ __forceinline__ uint32_t smem_to_u32(const void* p) {
    uint32_t a;
    asm("{ .reg .u64 t; cvta.to.shared.u64 t, %1; cvt.u32.u64 %0, t; }" : "=r"(a) : "l"(p));
    return a;
}
__device__ __forceinline__ void mma_16816_f16(float* c, const uint32_t* a, const uint32_t* b) {
    asm volatile(
        "mma.sync.aligned.m16n8k16.row.col.f32.f16.f16.f32 "
        "{%0,%1,%2,%3}, {%4,%5,%6,%7}, {%8,%9}, {%0,%1,%2,%3};"
        : "+f"(c[0]), "+f"(c[1]), "+f"(c[2]), "+f"(c[3])
        : "r"(a[0]), "r"(a[1]), "r"(a[2]), "r"(a[3]), "r"(b[0]), "r"(b[1]));
}
__device__ __forceinline__ void ldsm_x4_trans(uint32_t& r0, uint32_t& r1,
                                              uint32_t& r2, uint32_t& r3, uint32_t addr) {
    asm volatile("ldmatrix.sync.aligned.m8n8.x4.trans.shared.b16 {%0,%1,%2,%3}, [%4];"
                 : "=r"(r0), "=r"(r1), "=r"(r2), "=r"(r3) : "r"(addr));
}
#define CP_ASYNC_16(smem_u32, gptr) \
    asm volatile("cp.async.cg.shared.global [%0], [%1], 16;" :: "r"(smem_u32), "l"(gptr))
#define CP_ASYNC_COMMIT() asm volatile("cp.async.commit_group;")
#define CP_ASYNC_WAIT(n)  asm volatile("cp.async.wait_group %0;" :: "n"(n))

// ---------------------------------------------------------------------------
// zeroA: A row s=0 of each batch is zero (Qaddr shift boundary).
// ---------------------------------------------------------------------------
__global__ __launch_bounds__(256) void zeroA() {
    const int idx = blockIdx.x * 256 + threadIdx.x;     // < 8*512
    const int b = idx >> 9, col = idx & 511;
    const size_t o = (size_t)b * S_ * KDIM + col;
    g_Ahi[o] = __float2half(0.f);
}

// ---------------------------------------------------------------------------
// Kernel 1 (fused): per-(head, chunk) Gram partials via tensor cores AND the
// fp16 Qaddr A-matrix write (prepA fused into the load phase).
//   Rows enumerated r = b*4095 + i, i in 0..4094. A written for all valid i
//   (to row m = b*4096+i+1); MMA accumulates only i < 4094 (masked to zero).
// ---------------------------------------------------------------------------
#define RT 64       // rows per stage
#define RP 72       // padded halfs per smem row

__global__ __launch_bounds__(256, 2) void gram_mma(const float* __restrict__ Q,
                                                   const float* __restrict__ V) {
    const int c = blockIdx.x;   // chunk (1024 rows)
    const int h = blockIdx.y;
    const int t = threadIdx.x;
    const int wid = t >> 5, lane = t & 31;

    __shared__ __half Tqh[RT * RP];   // q_hat, k-major: [r][d]
    __shared__ __half Tq [RT * RP];   // q
    __shared__ __half Tv [RT * RP];   // v (shift+2)

    const uint32_t sTqh = smem_to_u32(Tqh);
    const uint32_t sTq  = smem_to_u32(Tq);
    const uint32_t sTv  = smem_to_u32(Tv);

    // load mapping: thread covers row lr = t>>2, col quarter tq = t&3 (16 cols)
    const int lr = t >> 2;
    const int tq = t & 3;

    // mma mapping
    const int p0 = 16 * (wid & 3);
    const uint32_t TA = (wid < 4) ? sTqh : sTq;
    const uint32_t TB = (wid < 4) ? sTqh : sTv;
    const int l8  = lane & 7;
    const int sub = lane >> 3;
    const uint32_t a_off = (uint32_t)((((sub >> 1) * 8 + l8) * RP + p0 + (sub & 1) * 8) * 2);
    const uint32_t b_off = (uint32_t)((((sub & 1) * 8 + l8) * RP + (sub >> 1) * 8) * 2);

    float acc[8][4];
#pragma unroll
    for (int i = 0; i < 8; ++i)
#pragma unroll
        for (int j = 0; j < 4; ++j) acc[i][j] = 0.f;

    for (int st = 0; st < GROWS / RT; ++st) {            // 16 stages
        const int gr = c * GROWS + st * RT + lr;
        float q[16], v[16];
#pragma unroll
        for (int i = 0; i < 16; ++i) { q[i] = 0.f; v[i] = 0.f; }
        const bool valid = (gr < ROWS_A);
        int b = 0, i = 0;
        if (valid) {
            b = gr / RPB;
            i = gr - b * RPB;                            // 0..4094
            const float* qrow = Q + (((size_t)(b * H_ + h)) * S_ + i) * D_ + tq * 16;
#pragma unroll
            for (int j = 0; j < 4; ++j)
                *(float4*)&q[j * 4] = *(const float4*)(qrow + j * 4);
            if (i < SM2) {
                const float* vrow = V + (((size_t)(b * H_ + h)) * S_ + i + 2) * D_ + tq * 16;
#pragma unroll
                for (int j = 0; j < 4; ++j)
                    *(float4*)&v[j * 4] = *(const float4*)(vrow + j * 4);
            }
        }
        // fp16 of raw q — doubles as the A-matrix payload (prepA fusion)
        __half2 hq[8];
#pragma unroll
        for (int j = 0; j < 8; ++j) hq[j] = __floats2half2_rn(q[2 * j], q[2 * j + 1]);
        if (valid) {
            __half* d = g_Ahi + (((size_t)(b * S_ + i + 1)) << 9) + h * 64 + tq * 16;
            *(uint4*)(d)     = *(uint4*)&hq[0];
            *(uint4*)(d + 8) = *(uint4*)&hq[4];
        }
        // mask A-only row (i == 4094) and out-of-range rows out of the MMA
        const bool active = valid && (i < SM2);
        if (!active) {
#pragma unroll
            for (int j = 0; j < 16; ++j) q[j] = 0.f;
#pragma unroll
            for (int j = 0; j < 8; ++j) hq[j] = __halves2half2(__half(0), __half(0));
        }
        // row norm across the 4 lanes covering this row
        float ss = 0.f;
#pragma unroll
        for (int j = 0; j < 16; ++j) ss += q[j] * q[j];
        ss += __shfl_xor_sync(0xffffffffu, ss, 1);
        ss += __shfl_xor_sync(0xffffffffu, ss, 2);
        const float inv = 1.0f / fmaxf(sqrtf(ss), 1e-8f);

        __half2 hqh[8], hv[8];
#pragma unroll
        for (int j = 0; j < 8; ++j) {
            hqh[j] = __floats2half2_rn(q[2 * j] * inv, q[2 * j + 1] * inv);
            hv[j]  = __floats2half2_rn(v[2 * j], v[2 * j + 1]);
        }
        __syncthreads();   // previous stage's mma reads done
        {
            __half* d0 = Tqh + lr * RP + tq * 16;
            *(uint4*)(d0)     = *(uint4*)&hqh[0];
            *(uint4*)(d0 + 8) = *(uint4*)&hqh[4];
            __half* d1 = Tq + lr * RP + tq * 16;
            *(uint4*)(d1)     = *(uint4*)&hq[0];
            *(uint4*)(d1 + 8) = *(uint4*)&hq[4];
            __half* d2 = Tv + lr * RP + tq * 16;
            *(uint4*)(d2)     = *(uint4*)&hv[0];
            *(uint4*)(d2 + 8) = *(uint4*)&hv[4];
        }
        __syncthreads();

#pragma unroll
        for (int ks = 0; ks < RT / 16; ++ks) {           // 4 k16-steps
            const uint32_t kb = (uint32_t)(ks * 16 * RP * 2);
            uint32_t a[4];
            ldsm_x4_trans(a[0], a[1], a[2], a[3], TA + kb + a_off);
#pragma unroll
            for (int nt = 0; nt < 8; nt += 2) {
                uint32_t b0, b1, b2, b3;
                ldsm_x4_trans(b0, b1, b2, b3, TB + kb + b_off + nt * 8 * 2);
                uint32_t bb0[2] = {b0, b1};
                uint32_t bb1[2] = {b2, b3};
                mma_16816_f16(acc[nt],     a, bb0);
                mma_16816_f16(acc[nt + 1], a, bb1);
            }
        }
    }

    // write partials
    float* o = g_scratch[h][c][(wid < 4) ? 0 : 1];
    const int fr = lane >> 2;
    const int c2 = (lane & 3) * 2;
#pragma unroll
    for (int nt = 0; nt < 8; ++nt) {
        const int col = nt * 8 + c2;
        *(float2*)&o[(p0 + fr) * 64 + col]     = make_float2(acc[nt][0], acc[nt][1]);
        *(float2*)&o[(p0 + fr + 8) * 64 + col] = make_float2(acc[nt][2], acc[nt][3]);
    }
}

// ---------------------------------------------------------------------------
// Kernel 2: reduce chunk partials.
// ---------------------------------------------------------------------------
__global__ __launch_bounds__(256) void reduce_gram() {
    const int h = blockIdx.y;
    const int e = blockIdx.x * 256 + threadIdx.x;
    float sg = 0.f, su = 0.f;
    for (int c = 0; c < GCH; ++c) {
        sg += g_scratch[h][c][0][e];
        su += g_scratch[h][c][1][e];
    }
    g_G[h][e] = sg;
    g_U[h][e] = su;
}

// ---------------------------------------------------------------------------
// Kernel 3: new_trace = 0.99*(trace - (G/denom)@trace) + 0.1*U/denom
// ---------------------------------------------------------------------------
__global__ __launch_bounds__(256) void combine_trace(const float* __restrict__ trace) {
    const int h = blockIdx.x;
    const int t = threadIdx.x;
    __shared__ float Gs[4096];
    __shared__ float Ts[4096];
#pragma unroll
    for (int j = 0; j < 16; ++j) {
        Gs[t + 256 * j] = g_G[h][t + 256 * j];
        Ts[t + 256 * j] = trace[h * 4096 + t + 256 * j];
    }
    __syncthreads();
    const float invd = 1.0f / DENOM;
#pragma unroll
    for (int j = 0; j < 16; ++j) {
        const int e = t + 256 * j;
        const int p = e >> 6, q = e & 63;
        float acc = 0.f;
#pragma unroll 8
        for (int k = 0; k < 64; ++k)
            acc += Gs[p * 64 + k] * Ts[k * 64 + q];
        g_NT[h][e] = 0.99f * (Ts[e] - acc * invd) + 0.1f * g_U[h][e] * invd;
    }
}

// ---------------------------------------------------------------------------
// Kernel 4: B[n][h*64+p] = sum_q NT[h][p][q] * W[n][h*64+q] -> fp16.
// ---------------------------------------------------------------------------
__global__ __launch_bounds__(256) void build_M(const float* __restrict__ W) {
    const int h  = blockIdx.y;
    const int n0 = blockIdx.x * 64;
    const int t  = threadIdx.x;
    __shared__ float Wq[64][72];   // [q][n]
    __shared__ float Nq[64][72];   // [q][p]
#pragma unroll
    for (int j = 0; j < 4; ++j) {
        const int idx = t + j * 256;
        const int row = idx >> 4;
        const int q4  = (idx & 15) * 4;
        float4 wv = *(const float4*)(W + (size_t)(n0 + row) * KDIM + h * 64 + q4);
        Wq[q4 + 0][row] = wv.x; Wq[q4 + 1][row] = wv.y;
        Wq[q4 + 2][row] = wv.z; Wq[q4 + 3][row] = wv.w;
        float4 nv = *(const float4*)(&g_NT[h][row * 64 + q4]);
        Nq[q4 + 0][row] = nv.x; Nq[q4 + 1][row] = nv.y;
        Nq[q4 + 2][row] = nv.z; Nq[q4 + 3][row] = nv.w;
    }
    __syncthreads();
    const int tx = t & 15;     // p block
    const int ty = t >> 4;     // n block
    float acc[4][4];
#pragma unroll
    for (int i = 0; i < 4; ++i)
#pragma unroll
        for (int j = 0; j < 4; ++j) acc[i][j] = 0.f;
#pragma unroll 8
    for (int q = 0; q < 64; ++q) {
        const float4 wv = *(const float4*)&Wq[q][ty * 4];
        const float4 nv = *(const float4*)&Nq[q][tx * 4];
        const float w[4] = {wv.x, wv.y, wv.z, wv.w};
        const float nn[4] = {nv.x, nv.y, nv.z, nv.w};
#pragma unroll
        for (int i = 0; i < 4; ++i)
#pragma unroll
            for (int j = 0; j < 4; ++j)
                acc[i][j] += w[i] * nn[j];
    }
#pragma unroll
    for (int i = 0; i < 4; ++i) {
        const int n = n0 + ty * 4 + i;
#pragma unroll
        for (int j = 0; j < 4; ++j) {
            const int k = h * 64 + tx * 4 + j;
            g_Bhi[(size_t)n * KDIM + k] = __float2half_rn(acc[i][j]);
        }
    }
}

// ---------------------------------------------------------------------------
// Kernel 5: out = Ahi @ Bhi^T via mma.sync fp16 (8 K-chunks) — EXACT R8/R11.
// ---------------------------------------------------------------------------
#define STG_BYTES 36864                         // (128*72 + 128*72) * 2B
#define GEMM_SMEM (2 * STG_BYTES)               // 73728

__global__ __launch_bounds__(256, 2) void out_gemm_mma(float* __restrict__ out) {
    extern __shared__ __align__(16) char smem[];
    const int t = threadIdx.x;
    const int n_base = blockIdx.x * 128;
    const int m_base = blockIdx.y * 128;
    const uint32_t sbase = smem_to_u32(smem);

    const int lrow = t >> 3;
    const int lc8  = t & 7;

    auto load_stage = [&](int kc, int stage) {
        const int k0 = kc * 64;
        const uint32_t sa = sbase + stage * STG_BYTES;
        const uint32_t sb = sa + 128 * 144;
#pragma unroll
        for (int i = 0; i < 4; ++i) {
            const int row = lrow + i * 32;
            const __half* g = g_Ahi + (((size_t)(m_base + row)) << 9) + k0 + lc8 * 8;
            CP_ASYNC_16(sa + row * 144 + lc8 * 16, g);
        }
#pragma unroll
        for (int i = 0; i < 4; ++i) {
            const int row = lrow + i * 32;
            const __half* g = g_Bhi + (((size_t)(n_base + row)) << 9) + k0 + lc8 * 8;
            CP_ASYNC_16(sb + row * 144 + lc8 * 16, g);
        }
        CP_ASYNC_COMMIT();
    };

    const int wid = t >> 5, lane = t & 31;
    const int wm = wid >> 2;
    const int wn = wid & 3;
    const int fr = lane >> 2;
    const int fcb = (lane & 3) * 4;

    float acc[4][4][4];
#pragma unroll
    for (int mi = 0; mi < 4; ++mi)
#pragma unroll
        for (int ni = 0; ni < 4; ++ni)
#pragma unroll
            for (int j = 0; j < 4; ++j) acc[mi][ni][j] = 0.f;

    load_stage(0, 0);
    for (int kc = 0; kc < 8; ++kc) {
        if (kc + 1 < 8) {
            load_stage(kc + 1, (kc + 1) & 1);
            CP_ASYNC_WAIT(1);
        } else {
            CP_ASYNC_WAIT(0);
        }
        __syncthreads();

        const char* As = smem + (kc & 1) * STG_BYTES;
        const char* Bs = As + 128 * 144;
#pragma unroll
        for (int kk = 0; kk < 4; ++kk) {
            const int cb = kk * 32 + fcb;
            uint32_t a[4][4];
#pragma unroll
            for (int mi = 0; mi < 4; ++mi) {
                const int r = wm * 64 + mi * 16 + fr;
                a[mi][0] = *(const uint32_t*)(As + r * 144 + cb);
                a[mi][1] = *(const uint32_t*)(As + (r + 8) * 144 + cb);
                a[mi][2] = *(const uint32_t*)(As + r * 144 + cb + 16);
                a[mi][3] = *(const uint32_t*)(As + (r + 8) * 144 + cb + 16);
            }
            uint32_t b[4][2];
#pragma unroll
            for (int ni = 0; ni < 4; ++ni) {
                const int n = wn * 32 + ni * 8 + fr;
                b[ni][0] = *(const uint32_t*)(Bs + n * 144 + cb);
                b[ni][1] = *(const uint32_t*)(Bs + n * 144 + cb + 16);
            }
#pragma unroll
            for (int mi = 0; mi < 4; ++mi)
#pragma unroll
                for (int ni = 0; ni < 4; ++ni)
                    mma_16816_f16(acc[mi][ni], a[mi], b[ni]);
        }
        __syncthreads();
    }

#pragma unroll
    for (int mi = 0; mi < 4; ++mi) {
        const int r = m_base + wm * 64 + mi * 16 + fr;
#pragma unroll
        for (int ni = 0; ni < 4; ++ni) {
            const int cg = n_base + wn * 32 + ni * 8 + (lane & 3) * 2;
            *(float2*)(out + (size_t)r * DM_ + cg) =
                make_float2(acc[mi][ni][0], acc[mi][ni][1]);
            *(float2*)(out + (size_t)(r + 8) * DM_ + cg) =
                make_float2(acc[mi][ni][2], acc[mi][ni][3]);
        }
    }
}

// ---------------------------------------------------------------------------
extern "C" void kernel_launch(void* const* d_in, const int* in_sizes, int n_in,
                              void* d_out, int out_size) {
    const float* Q     = (const float*)d_in[0];
    const float* V     = (const float*)d_in[1];
    const float* trace = (const float*)d_in[2];
    const float* W     = (const float*)d_in[3];
    float* out = (float*)d_out;

    static bool attr_set = false;
    if (!attr_set) {
        cudaFuncSetAttribute(out_gemm_mma, cudaFuncAttributeMaxDynamicSharedMemorySize, GEMM_SMEM);
        attr_set = true;
    }

    zeroA<<<(B_ * KDIM) / 256, 256>>>();
    gram_mma<<<dim3(GCH, H_), 256>>>(Q, V);
    reduce_gram<<<dim3(16, H_), 256>>>();
    combine_trace<<<H_, 256>>>(trace);
    build_M<<<dim3(12, H_), 256>>>(W);
    out_gemm_mma<<<dim3(DM_ / 128, MROWS / 128), 256, GEMM_SMEM>>>(out);
}

// round 13
// speedup vs baseline: 3.5540x; 1.0523x over previous
#include <cuda_runtime.h>
#include <cuda_fp16.h>
#include <cstdint>

// Problem constants
#define B_   8
#define H_   8
#define S_   4096
#define D_   64
#define DM_  768
#define SM2  (S_ - 2)            // 4094 (rows entering the Hebbian update)
#define RPB  (S_ - 1)            // 4095 (rows per batch incl. A-only row i=4094)
#define ROWS_A (B_ * RPB)        // 32760
#define DENOM ((float)(B_ * SM2))

#define GCH   32                 // gram chunks
#define GROWS 1024               // rows per chunk

#define MROWS (B_ * S_)          // 32768
#define KDIM  (H_ * D_)          // 512

// ---------------------------------------------------------------------------
// Static device scratch (allocation-free per harness rules)
// ---------------------------------------------------------------------------
__device__ float g_scratch[H_][GCH][2][D_ * D_];
__device__ float g_NT[H_][D_ * D_];
__device__ __align__(16) __half g_Ahi[(size_t)MROWS * KDIM];
__device__ __align__(16) __half g_Bhi[(size_t)DM_ * KDIM];

// ---------------------------------------------------------------------------
// Helpers
// ---------------------------------------------------------------------------
__device__ __forceinline__ uint32_t smem_to_u32(const void* p) {
    uint32_t a;
    asm("{ .reg .u64 t; cvta.to.shared.u64 t, %1; cvt.u32.u64 %0, t; }" : "=r"(a) : "l"(p));
    return a;
}
__device__ __forceinline__ void mma_16816_f16(float* c, const uint32_t* a, const uint32_t* b) {
    asm volatile(
        "mma.sync.aligned.m16n8k16.row.col.f32.f16.f16.f32 "
        "{%0,%1,%2,%3}, {%4,%5,%6,%7}, {%8,%9}, {%0,%1,%2,%3};"
        : "+f"(c[0]), "+f"(c[1]), "+f"(c[2]), "+f"(c[3])
        : "r"(a[0]), "r"(a[1]), "r"(a[2]), "r"(a[3]), "r"(b[0]), "r"(b[1]));
}
__device__ __forceinline__ void ldsm_x4_trans(uint32_t& r0, uint32_t& r1,
                                              uint32_t& r2, uint32_t& r3, uint32_t addr) {
    asm volatile("ldmatrix.sync.aligned.m8n8.x4.trans.shared.b16 {%0,%1,%2,%3}, [%4];"
                 : "=r"(r0), "=r"(r1), "=r"(r2), "=r"(r3) : "r"(addr));
}
#define CP_ASYNC_16(smem_u32, gptr) \
    asm volatile("cp.async.cg.shared.global [%0], [%1], 16;" :: "r"(smem_u32), "l"(gptr))
#define CP_ASYNC_COMMIT() asm volatile("cp.async.commit_group;")
#define CP_ASYNC_WAIT(n)  asm volatile("cp.async.wait_group %0;" :: "n"(n))

// ---------------------------------------------------------------------------
// zeroA: A row s=0 of each batch is zero (Qaddr shift boundary).
// ---------------------------------------------------------------------------
__global__ __launch_bounds__(256) void zeroA() {
    const int idx = blockIdx.x * 256 + threadIdx.x;     // < 8*512
    const int b = idx >> 9, col = idx & 511;
    const size_t o = (size_t)b * S_ * KDIM + col;
    g_Ahi[o] = __float2half(0.f);
}

// ---------------------------------------------------------------------------
// Kernel 1 (fused): per-(head, chunk) Gram partials via tensor cores AND the
// fp16 Qaddr A-matrix write (prepA fused into the load phase). EXACT R12.
// ---------------------------------------------------------------------------
#define RT 64       // rows per stage
#define RP 72       // padded halfs per smem row

__global__ __launch_bounds__(256, 2) void gram_mma(const float* __restrict__ Q,
                                                   const float* __restrict__ V) {
    const int c = blockIdx.x;   // chunk (1024 rows)
    const int h = blockIdx.y;
    const int t = threadIdx.x;
    const int wid = t >> 5, lane = t & 31;

    __shared__ __half Tqh[RT * RP];   // q_hat, k-major: [r][d]
    __shared__ __half Tq [RT * RP];   // q
    __shared__ __half Tv [RT * RP];   // v (shift+2)

    const uint32_t sTqh = smem_to_u32(Tqh);
    const uint32_t sTq  = smem_to_u32(Tq);
    const uint32_t sTv  = smem_to_u32(Tv);

    const int lr = t >> 2;
    const int tq = t & 3;

    const int p0 = 16 * (wid & 3);
    const uint32_t TA = (wid < 4) ? sTqh : sTq;
    const uint32_t TB = (wid < 4) ? sTqh : sTv;
    const int l8  = lane & 7;
    const int sub = lane >> 3;
    const uint32_t a_off = (uint32_t)((((sub >> 1) * 8 + l8) * RP + p0 + (sub & 1) * 8) * 2);
    const uint32_t b_off = (uint32_t)((((sub & 1) * 8 + l8) * RP + (sub >> 1) * 8) * 2);

    float acc[8][4];
#pragma unroll
    for (int i = 0; i < 8; ++i)
#pragma unroll
        for (int j = 0; j < 4; ++j) acc[i][j] = 0.f;

    for (int st = 0; st < GROWS / RT; ++st) {            // 16 stages
        const int gr = c * GROWS + st * RT + lr;
        float q[16], v[16];
#pragma unroll
        for (int i = 0; i < 16; ++i) { q[i] = 0.f; v[i] = 0.f; }
        const bool valid = (gr < ROWS_A);
        int b = 0, i = 0;
        if (valid) {
            b = gr / RPB;
            i = gr - b * RPB;                            // 0..4094
            const float* qrow = Q + (((size_t)(b * H_ + h)) * S_ + i) * D_ + tq * 16;
#pragma unroll
            for (int j = 0; j < 4; ++j)
                *(float4*)&q[j * 4] = *(const float4*)(qrow + j * 4);
            if (i < SM2) {
                const float* vrow = V + (((size_t)(b * H_ + h)) * S_ + i + 2) * D_ + tq * 16;
#pragma unroll
                for (int j = 0; j < 4; ++j)
                    *(float4*)&v[j * 4] = *(const float4*)(vrow + j * 4);
            }
        }
        // fp16 of raw q — doubles as the A-matrix payload (prepA fusion)
        __half2 hq[8];
#pragma unroll
        for (int j = 0; j < 8; ++j) hq[j] = __floats2half2_rn(q[2 * j], q[2 * j + 1]);
        if (valid) {
            __half* d = g_Ahi + (((size_t)(b * S_ + i + 1)) << 9) + h * 64 + tq * 16;
            *(uint4*)(d)     = *(uint4*)&hq[0];
            *(uint4*)(d + 8) = *(uint4*)&hq[4];
        }
        // mask A-only row (i == 4094) and out-of-range rows out of the MMA
        const bool active = valid && (i < SM2);
        if (!active) {
#pragma unroll
            for (int j = 0; j < 16; ++j) q[j] = 0.f;
#pragma unroll
            for (int j = 0; j < 8; ++j) hq[j] = __halves2half2(__half(0), __half(0));
        }
        // row norm across the 4 lanes covering this row
        float ss = 0.f;
#pragma unroll
        for (int j = 0; j < 16; ++j) ss += q[j] * q[j];
        ss += __shfl_xor_sync(0xffffffffu, ss, 1);
        ss += __shfl_xor_sync(0xffffffffu, ss, 2);
        const float inv = 1.0f / fmaxf(sqrtf(ss), 1e-8f);

        __half2 hqh[8], hv[8];
#pragma unroll
        for (int j = 0; j < 8; ++j) {
            hqh[j] = __floats2half2_rn(q[2 * j] * inv, q[2 * j + 1] * inv);
            hv[j]  = __floats2half2_rn(v[2 * j], v[2 * j + 1]);
        }
        __syncthreads();   // previous stage's mma reads done
        {
            __half* d0 = Tqh + lr * RP + tq * 16;
            *(uint4*)(d0)     = *(uint4*)&hqh[0];
            *(uint4*)(d0 + 8) = *(uint4*)&hqh[4];
            __half* d1 = Tq + lr * RP + tq * 16;
            *(uint4*)(d1)     = *(uint4*)&hq[0];
            *(uint4*)(d1 + 8) = *(uint4*)&hq[4];
            __half* d2 = Tv + lr * RP + tq * 16;
            *(uint4*)(d2)     = *(uint4*)&hv[0];
            *(uint4*)(d2 + 8) = *(uint4*)&hv[4];
        }
        __syncthreads();

#pragma unroll
        for (int ks = 0; ks < RT / 16; ++ks) {           // 4 k16-steps
            const uint32_t kb = (uint32_t)(ks * 16 * RP * 2);
            uint32_t a[4];
            ldsm_x4_trans(a[0], a[1], a[2], a[3], TA + kb + a_off);
#pragma unroll
            for (int nt = 0; nt < 8; nt += 2) {
                uint32_t b0, b1, b2, b3;
                ldsm_x4_trans(b0, b1, b2, b3, TB + kb + b_off + nt * 8 * 2);
                uint32_t bb0[2] = {b0, b1};
                uint32_t bb1[2] = {b2, b3};
                mma_16816_f16(acc[nt],     a, bb0);
                mma_16816_f16(acc[nt + 1], a, bb1);
            }
        }
    }

    // write partials
    float* o = g_scratch[h][c][(wid < 4) ? 0 : 1];
    const int fr = lane >> 2;
    const int c2 = (lane & 3) * 2;
#pragma unroll
    for (int nt = 0; nt < 8; ++nt) {
        const int col = nt * 8 + c2;
        *(float2*)&o[(p0 + fr) * 64 + col]     = make_float2(acc[nt][0], acc[nt][1]);
        *(float2*)&o[(p0 + fr + 8) * 64 + col] = make_float2(acc[nt][2], acc[nt][3]);
    }
}

// ---------------------------------------------------------------------------
// Kernel 2 (fused reduce + combine): grid (8 p-blocks, 8 heads), 256 thr.
// Each block reduces its 8 G/U rows over the 32 chunks (sequential order —
// bit-identical to the old reduce_gram) and computes
//   NT[p][q] = 0.99*(T[p][q] - (G@T)[p][q]/denom) + 0.1*U[p][q]/denom.
// ---------------------------------------------------------------------------
__global__ __launch_bounds__(256) void reduce_combine(const float* __restrict__ trace) {
    const int h  = blockIdx.y;
    const int p0 = blockIdx.x * 8;
    const int t  = threadIdx.x;

    __shared__ float Ts[4096];      // full trace for head: [k][q]
    __shared__ float Gs[8 * 64];    // reduced G rows p0..p0+7
    __shared__ float Us[8 * 64];

#pragma unroll
    for (int j = 0; j < 16; ++j)
        Ts[t + 256 * j] = trace[h * 4096 + t + 256 * j];

#pragma unroll
    for (int j = 0; j < 2; ++j) {
        const int e   = t + 256 * j;        // 0..511
        const int idx = p0 * 64 + e;        // element within 64x64 matrix
        float sg = 0.f, su = 0.f;
#pragma unroll 4
        for (int c = 0; c < GCH; ++c) {
            sg += g_scratch[h][c][0][idx];
            su += g_scratch[h][c][1][idx];
        }
        Gs[e] = sg;
        Us[e] = su;
    }
    __syncthreads();

    const float invd = 1.0f / DENOM;
#pragma unroll
    for (int j = 0; j < 2; ++j) {
        const int e  = t + 256 * j;
        const int pl = e >> 6, q = e & 63;
        float acc = 0.f;
#pragma unroll 8
        for (int k = 0; k < 64; ++k)
            acc += Gs[pl * 64 + k] * Ts[k * 64 + q];
        g_NT[h][(p0 + pl) * 64 + q] =
            0.99f * (Ts[(p0 + pl) * 64 + q] - acc * invd) + 0.1f * Us[e] * invd;
    }
}

// ---------------------------------------------------------------------------
// Kernel 3: B[n][h*64+p] = sum_q NT[h][p][q] * W[n][h*64+q] -> fp16. EXACT R12.
// ---------------------------------------------------------------------------
__global__ __launch_bounds__(256) void build_M(const float* __restrict__ W) {
    const int h  = blockIdx.y;
    const int n0 = blockIdx.x * 64;
    const int t  = threadIdx.x;
    __shared__ float Wq[64][72];   // [q][n]
    __shared__ float Nq[64][72];   // [q][p]
#pragma unroll
    for (int j = 0; j < 4; ++j) {
        const int idx = t + j * 256;
        const int row = idx >> 4;
        const int q4  = (idx & 15) * 4;
        float4 wv = *(const float4*)(W + (size_t)(n0 + row) * KDIM + h * 64 + q4);
        Wq[q4 + 0][row] = wv.x; Wq[q4 + 1][row] = wv.y;
        Wq[q4 + 2][row] = wv.z; Wq[q4 + 3][row] = wv.w;
        float4 nv = *(const float4*)(&g_NT[h][row * 64 + q4]);
        Nq[q4 + 0][row] = nv.x; Nq[q4 + 1][row] = nv.y;
        Nq[q4 + 2][row] = nv.z; Nq[q4 + 3][row] = nv.w;
    }
    __syncthreads();
    const int tx = t & 15;     // p block
    const int ty = t >> 4;     // n block
    float acc[4][4];
#pragma unroll
    for (int i = 0; i < 4; ++i)
#pragma unroll
        for (int j = 0; j < 4; ++j) acc[i][j] = 0.f;
#pragma unroll 8
    for (int q = 0; q < 64; ++q) {
        const float4 wv = *(const float4*)&Wq[q][ty * 4];
        const float4 nv = *(const float4*)&Nq[q][tx * 4];
        const float w[4] = {wv.x, wv.y, wv.z, wv.w};
        const float nn[4] = {nv.x, nv.y, nv.z, nv.w};
#pragma unroll
        for (int i = 0; i < 4; ++i)
#pragma unroll
            for (int j = 0; j < 4; ++j)
                acc[i][j] += w[i] * nn[j];
    }
#pragma unroll
    for (int i = 0; i < 4; ++i) {
        const int n = n0 + ty * 4 + i;
#pragma unroll
        for (int j = 0; j < 4; ++j) {
            const int k = h * 64 + tx * 4 + j;
            g_Bhi[(size_t)n * KDIM + k] = __float2half_rn(acc[i][j]);
        }
    }
}

// ---------------------------------------------------------------------------
// Kernel 4: out = Ahi @ Bhi^T via mma.sync fp16 (8 K-chunks) — EXACT R8/R12.
// ---------------------------------------------------------------------------
#define STG_BYTES 36864                         // (128*72 + 128*72) * 2B
#define GEMM_SMEM (2 * STG_BYTES)               // 73728

__global__ __launch_bounds__(256, 2) void out_gemm_mma(float* __restrict__ out) {
    extern __shared__ __align__(16) char smem[];
    const int t = threadIdx.x;
    const int n_base = blockIdx.x * 128;
    const int m_base = blockIdx.y * 128;
    const uint32_t sbase = smem_to_u32(smem);

    const int lrow = t >> 3;
    const int lc8  = t & 7;

    auto load_stage = [&](int kc, int stage) {
        const int k0 = kc * 64;
        const uint32_t sa = sbase + stage * STG_BYTES;
        const uint32_t sb = sa + 128 * 144;
#pragma unroll
        for (int i = 0; i < 4; ++i) {
            const int row = lrow + i * 32;
            const __half* g = g_Ahi + (((size_t)(m_base + row)) << 9) + k0 + lc8 * 8;
            CP_ASYNC_16(sa + row * 144 + lc8 * 16, g);
        }
#pragma unroll
        for (int i = 0; i < 4; ++i) {
            const int row = lrow + i * 32;
            const __half* g = g_Bhi + (((size_t)(n_base + row)) << 9) + k0 + lc8 * 8;
            CP_ASYNC_16(sb + row * 144 + lc8 * 16, g);
        }
        CP_ASYNC_COMMIT();
    };

    const int wid = t >> 5, lane = t & 31;
    const int wm = wid >> 2;
    const int wn = wid & 3;
    const int fr = lane >> 2;
    const int fcb = (lane & 3) * 4;

    float acc[4][4][4];
#pragma unroll
    for (int mi = 0; mi < 4; ++mi)
#pragma unroll
        for (int ni = 0; ni < 4; ++ni)
#pragma unroll
            for (int j = 0; j < 4; ++j) acc[mi][ni][j] = 0.f;

    load_stage(0, 0);
    for (int kc = 0; kc < 8; ++kc) {
        if (kc + 1 < 8) {
            load_stage(kc + 1, (kc + 1) & 1);
            CP_ASYNC_WAIT(1);
        } else {
            CP_ASYNC_WAIT(0);
        }
        __syncthreads();

        const char* As = smem + (kc & 1) * STG_BYTES;
        const char* Bs = As + 128 * 144;
#pragma unroll
        for (int kk = 0; kk < 4; ++kk) {
            const int cb = kk * 32 + fcb;
            uint32_t a[4][4];
#pragma unroll
            for (int mi = 0; mi < 4; ++mi) {
                const int r = wm * 64 + mi * 16 + fr;
                a[mi][0] = *(const uint32_t*)(As + r * 144 + cb);
                a[mi][1] = *(const uint32_t*)(As + (r + 8) * 144 + cb);
                a[mi][2] = *(const uint32_t*)(As + r * 144 + cb + 16);
                a[mi][3] = *(const uint32_t*)(As + (r + 8) * 144 + cb + 16);
            }
            uint32_t b[4][2];
#pragma unroll
            for (int ni = 0; ni < 4; ++ni) {
                const int n = wn * 32 + ni * 8 + fr;
                b[ni][0] = *(const uint32_t*)(Bs + n * 144 + cb);
                b[ni][1] = *(const uint32_t*)(Bs + n * 144 + cb + 16);
            }
#pragma unroll
            for (int mi = 0; mi < 4; ++mi)
#pragma unroll
                for (int ni = 0; ni < 4; ++ni)
                    mma_16816_f16(acc[mi][ni], a[mi], b[ni]);
        }
        __syncthreads();
    }

#pragma unroll
    for (int mi = 0; mi < 4; ++mi) {
        const int r = m_base + wm * 64 + mi * 16 + fr;
#pragma unroll
        for (int ni = 0; ni < 4; ++ni) {
            const int cg = n_base + wn * 32 + ni * 8 + (lane & 3) * 2;
            *(float2*)(out + (size_t)r * DM_ + cg) =
                make_float2(acc[mi][ni][0], acc[mi][ni][1]);
            *(float2*)(out + (size_t)(r + 8) * DM_ + cg) =
                make_float2(acc[mi][ni][2], acc[mi][ni][3]);
        }
    }
}

// ---------------------------------------------------------------------------
extern "C" void kernel_launch(void* const* d_in, const int* in_sizes, int n_in,
                              void* d_out, int out_size) {
    const float* Q     = (const float*)d_in[0];
    const float* V     = (const float*)d_in[1];
    const float* trace = (const float*)d_in[2];
    const float* W     = (const float*)d_in[3];
    float* out = (float*)d_out;

    static bool attr_set = false;
    if (!attr_set) {
        cudaFuncSetAttribute(out_gemm_mma, cudaFuncAttributeMaxDynamicSharedMemorySize, GEMM_SMEM);
        attr_set = true;
    }

    zeroA<<<(B_ * KDIM) / 256, 256>>>();
    gram_mma<<<dim3(GCH, H_), 256>>>(Q, V);
    reduce_combine<<<dim3(8, H_), 256>>>(trace);
    build_M<<<dim3(12, H_), 256>>>(W);
    out_gemm_mma<<<dim3(DM_ / 128, MROWS / 128), 256, GEMM_SMEM>>>(out);
}